// round 2
// baseline (speedup 1.0000x reference)
#include <cuda_runtime.h>
#include <cuda_bf16.h>

#define NN 262144
#define EE 4194304
#define DD 8
#define HH 32
#define LL 4
#define BN_EPS 1e-5f

// ---------------- scratch (device globals; no allocation allowed) ----------------
__device__ float  g_h[NN * 32];     // current layer input (stride 9 for layer 0, else 32)
__device__ float  g_agg[NN * 32];   // aggregation buffer
__device__ float  g_z[NN * 32];     // pre-BN MLP output
__device__ float  g_xs[NN * 128];   // JK concat buffer
__device__ double g_stats[64];      // [0:32) sum, [32:64) sumsq

static inline int cdiv(int a, int b) { return (a + b - 1) / b; }

// ---------------- kernels ----------------

// h0[n*9 + c] = c<8 ? x[n*8+c] : t
__global__ void k_init(const float* __restrict__ x, const float* __restrict__ t) {
    int i = blockIdx.x * blockDim.x + threadIdx.x;
    if (i >= NN * 9) return;
    int n = i / 9;
    int c = i - n * 9;
    g_h[i] = (c < 8) ? x[n * 8 + c] : t[0];
}

// zero agg[0:cnt) and stats[0:64)
__global__ void k_zero(int cnt) {
    int i = blockIdx.x * blockDim.x + threadIdx.x;
    if (i < cnt) g_agg[i] = 0.0f;
    if (i < 64)  g_stats[i] = 0.0;
}

template <int K>
__global__ void k_scatter(const int* __restrict__ src, const int* __restrict__ dst) {
    int i = blockIdx.x * blockDim.x + threadIdx.x;
    if (i >= EE * K) return;
    int e = i / K;
    int k = i - e * K;
    int s = src[e];
    int d = dst[e];
    atomicAdd(&g_agg[d * K + k], g_h[s * K + k]);
}

// warp-per-node 2-layer MLP: z = relu((1+eps)*h+agg @ W1 + b1) @ W2 + b2
template <int KIN>
__global__ void k_mlp(const float* __restrict__ W1, const float* __restrict__ b1,
                      const float* __restrict__ W2, const float* __restrict__ b2,
                      const float* __restrict__ epsp, int layer) {
    __shared__ float sW1[KIN * 32];
    __shared__ float sW2[32 * 32];
    __shared__ float sb1[32];
    __shared__ float sb2[32];
    for (int i = threadIdx.x; i < KIN * 32; i += blockDim.x) sW1[i] = W1[i];
    for (int i = threadIdx.x; i < 32 * 32; i += blockDim.x) sW2[i] = W2[i];
    if (threadIdx.x < 32) {
        sb1[threadIdx.x] = b1[threadIdx.x];
        sb2[threadIdx.x] = b2[threadIdx.x];
    }
    __syncthreads();

    int gwarp = (blockIdx.x * blockDim.x + threadIdx.x) >> 5;   // node id (grid sized exactly)
    int lane  = threadIdx.x & 31;
    float eps1 = 1.0f + epsp[layer];

    float zin = 0.0f;
    if (lane < KIN) {
        int idx = gwarp * KIN + lane;
        zin = eps1 * g_h[idx] + g_agg[idx];
    }
    float acc = sb1[lane];
#pragma unroll
    for (int k = 0; k < KIN; k++)
        acc = fmaf(__shfl_sync(0xffffffffu, zin, k), sW1[k * 32 + lane], acc);
    acc = fmaxf(acc, 0.0f);
    float acc2 = sb2[lane];
#pragma unroll
    for (int k = 0; k < 32; k++)
        acc2 = fmaf(__shfl_sync(0xffffffffu, acc, k), sW2[k * 32 + lane], acc2);
    g_z[gwarp * 32 + lane] = acc2;
}

// per-channel sum & sumsq of g_z  (gridDim*blockDim must be a multiple of 32)
__global__ void k_stats() {
    int tid    = threadIdx.x;
    int gtid   = blockIdx.x * blockDim.x + tid;
    int stride = gridDim.x * blockDim.x;
    float sum = 0.0f, sq = 0.0f;
    for (int i = gtid; i < NN * 32; i += stride) {
        float v = g_z[i];
        sum += v;
        sq  = fmaf(v, v, sq);
    }
    __shared__ float s_sum[256];
    __shared__ float s_sq[256];
    s_sum[tid] = sum;
    s_sq[tid]  = sq;
    __syncthreads();
    for (int off = 128; off >= 32; off >>= 1) {
        if (tid < off) {
            s_sum[tid] += s_sum[tid + off];
            s_sq[tid]  += s_sq[tid + off];
        }
        __syncthreads();
    }
    if (tid < 32) {
        atomicAdd(&g_stats[tid],      (double)s_sum[tid]);
        atomicAdd(&g_stats[32 + tid], (double)s_sq[tid]);
    }
}

// BN + ReLU; write h (stride 32) and xs slice
__global__ void k_bn_apply(const float* __restrict__ gamma, const float* __restrict__ beta,
                           int layer) {
    int i = blockIdx.x * blockDim.x + threadIdx.x;
    if (i >= NN * 32) return;
    int ch   = i & 31;
    int node = i >> 5;
    float mu  = (float)(g_stats[ch] / (double)NN);
    float var = (float)(g_stats[32 + ch] / (double)NN) - mu * mu;
    float scale = gamma[ch] * rsqrtf(var + BN_EPS);
    float shift = beta[ch] - mu * scale;
    float v = fmaxf(fmaf(g_z[i], scale, shift), 0.0f);
    g_h[i] = v;
    g_xs[node * 128 + layer * 32 + ch] = v;
}

// warp-per-node: new_x = xs_row(128) @ lin_W(128x8) + lin_b; masked writeback
__global__ void k_final(const float* __restrict__ linW, const float* __restrict__ linb,
                        const float* __restrict__ x,
                        const int* __restrict__ nmask,
                        const int* __restrict__ emask,
                        const int* __restrict__ ondp, const int* __restrict__ oedp,
                        float* __restrict__ out) {
    __shared__ float sW[128 * 8];
    for (int i = threadIdx.x; i < 128 * 8; i += blockDim.x) sW[i] = linW[i];
    __syncthreads();

    int node = (blockIdx.x * blockDim.x + threadIdx.x) >> 5;
    int lane = threadIdx.x & 31;

    float acc[8];
#pragma unroll
    for (int o = 0; o < 8; o++) acc[o] = 0.0f;
#pragma unroll
    for (int j = 0; j < 4; j++) {
        int k = j * 32 + lane;
        float v = g_xs[node * 128 + k];
#pragma unroll
        for (int o = 0; o < 8; o++)
            acc[o] = fmaf(v, sW[k * 8 + o], acc[o]);
    }
#pragma unroll
    for (int off = 16; off > 0; off >>= 1) {
#pragma unroll
        for (int o = 0; o < 8; o++)
            acc[o] += __shfl_xor_sync(0xffffffffu, acc[o], off);
    }
    if (lane < 8) {
        int c = lane;
        float nv = acc[c] + linb[c];
        int ond = ondp[0];
        int oed = oedp[0];
        bool nm = nmask[node] != 0;
        bool em = emask[node] != 0;
        bool take = (nm && c >= 1 && c < ond + 1) || (em && c >= 1 && c < oed + 1);
        out[node * 8 + c] = take ? nv : x[node * 8 + c];
    }
}

// ---------------- launch ----------------
extern "C" void kernel_launch(void* const* d_in, const int* in_sizes, int n_in,
                              void* d_out, int out_size) {
    const float* x     = (const float*)d_in[0];
    const float* t     = (const float*)d_in[1];
    const int*   ei    = (const int*)d_in[2];
    const int*   nmask = (const int*)d_in[3];
    const int*   emask = (const int*)d_in[4];
    const int*   ondp  = (const int*)d_in[5];
    const int*   oedp  = (const int*)d_in[6];
    const float* W1f   = (const float*)d_in[7];
    const float* b1f   = (const float*)d_in[8];
    const float* W2f   = (const float*)d_in[9];
    const float* b2f   = (const float*)d_in[10];
    const float* W1r   = (const float*)d_in[11];
    const float* b1r   = (const float*)d_in[12];
    const float* W2r   = (const float*)d_in[13];
    const float* b2r   = (const float*)d_in[14];
    const float* eps   = (const float*)d_in[15];
    const float* gamma = (const float*)d_in[16];
    const float* beta  = (const float*)d_in[17];
    const float* linW  = (const float*)d_in[18];
    const float* linb  = (const float*)d_in[19];
    float*       out   = (float*)d_out;

    const int* src = ei;
    const int* dst = ei + EE;

    const int TB = 256;

    k_init<<<cdiv(NN * 9, TB), TB>>>(x, t);

    for (int l = 0; l < LL; l++) {
        int K = (l == 0) ? 9 : 32;
        k_zero<<<cdiv(NN * K, TB), TB>>>(NN * K);
        if (l == 0) {
            k_scatter<9><<<cdiv(EE * 9, TB), TB>>>(src, dst);
            k_mlp<9><<<NN / 8, TB>>>(W1f, b1f, W2f, b2f, eps, 0);
        } else {
            k_scatter<32><<<cdiv(EE * 32, TB), TB>>>(src, dst);
            k_mlp<32><<<NN / 8, TB>>>(W1r + (l - 1) * 1024, b1r + (l - 1) * 32,
                                      W2r + (l - 1) * 1024, b2r + (l - 1) * 32, eps, l);
        }
        k_stats<<<1024, 256>>>();
        k_bn_apply<<<NN * 32 / TB, TB>>>(gamma + l * 32, beta + l * 32, l);
    }

    k_final<<<NN / 8, TB>>>(linW, linb, x, nmask, emask, ondp, oedp, out);
}

// round 3
// speedup vs baseline: 1.8118x; 1.8118x over previous
#include <cuda_runtime.h>
#include <cuda_bf16.h>

#define NN 262144
#define EE 4194304
#define LL 4
#define BN_EPS 1e-5f

// ---------------- scratch (device globals) ----------------
__device__ float  g_h[NN * 32];     // layer input (stride 9 for layer 0, else 32)
__device__ float  g_z[NN * 32];     // pre-BN MLP output
__device__ float  g_xs[NN * 128];   // JK concat buffer
__device__ double g_stats[64];      // [0:32) sum, [32:64) sumsq
// CSR scratch
__device__ int    g_cnt[NN];
__device__ int    g_row[NN + 1];
__device__ int    g_ofs[NN];
__device__ int    g_srcs[EE];
__device__ int    g_bsum[256];

static inline int cdiv(int a, int b) { return (a + b - 1) / b; }

// ---------------- init ----------------
__global__ void k_init(const float* __restrict__ x, const float* __restrict__ t) {
    int i = blockIdx.x * blockDim.x + threadIdx.x;
    if (i >= NN * 9) return;
    int n = i / 9;
    int c = i - n * 9;
    g_h[i] = (c < 8) ? x[n * 8 + c] : t[0];
}

// ---------------- CSR build ----------------
__global__ void k_zero_cnt() {
    int i = blockIdx.x * blockDim.x + threadIdx.x;
    if (i < NN) g_cnt[i] = 0;
}

__global__ void k_hist(const int* __restrict__ dst) {
    int i = blockIdx.x * blockDim.x + threadIdx.x;
    if (i < EE) atomicAdd(&g_cnt[dst[i]], 1);
}

// 256 blocks x 1024 threads: per-block inclusive scan; write (incl - own) = local excl
__global__ void k_scan1() {
    __shared__ int s[1024];
    int tid = threadIdx.x;
    int i = blockIdx.x * 1024 + tid;
    int v = g_cnt[i];
    s[tid] = v;
    __syncthreads();
    for (int off = 1; off < 1024; off <<= 1) {
        int t = (tid >= off) ? s[tid - off] : 0;
        __syncthreads();
        s[tid] += t;
        __syncthreads();
    }
    g_row[i] = s[tid] - v;
    if (tid == 1023) g_bsum[blockIdx.x] = s[1023];
}

// 1 block x 256: exclusive scan of block sums (in place)
__global__ void k_scan2() {
    __shared__ int s[256];
    int tid = threadIdx.x;
    int v = g_bsum[tid];
    s[tid] = v;
    __syncthreads();
    for (int off = 1; off < 256; off <<= 1) {
        int t = (tid >= off) ? s[tid - off] : 0;
        __syncthreads();
        s[tid] += t;
        __syncthreads();
    }
    g_bsum[tid] = s[tid] - v;   // exclusive
    if (tid == 0) g_row[NN] = EE;
}

__global__ void k_scan3() {
    int i = blockIdx.x * blockDim.x + threadIdx.x;
    if (i >= NN) return;
    int v = g_row[i] + g_bsum[i >> 10];
    g_row[i] = v;
    g_ofs[i] = v;
}

__global__ void k_fill(const int* __restrict__ src, const int* __restrict__ dst) {
    int i = blockIdx.x * blockDim.x + threadIdx.x;
    if (i >= EE) return;
    int pos = atomicAdd(&g_ofs[dst[i]], 1);
    g_srcs[pos] = src[i];
}

// ---------------- fused aggregate + 2-layer MLP (warp per node) ----------------
// KIN = input width (9 or 32), KP = KIN padded to mult of 4
template <int KIN, int KP>
__global__ void k_agg_mlp(const float* __restrict__ W1, const float* __restrict__ b1,
                          const float* __restrict__ W2, const float* __restrict__ b2,
                          const float* __restrict__ epsp, int layer) {
    __shared__ __align__(16) float sW1T[32 * 36];   // [out_j][k] padded stride 36
    __shared__ __align__(16) float sW2T[32 * 36];
    __shared__ __align__(16) float sZ[8 * 36];
    __shared__ float sb1[32], sb2[32];
    __shared__ int   sE[8 * 32];

    int tid = threadIdx.x;
    for (int i = tid; i < 32 * KP; i += blockDim.x) {
        int j = i / KP, k = i - j * KP;
        sW1T[j * 36 + k] = (k < KIN) ? W1[k * 32 + j] : 0.0f;
    }
    for (int i = tid; i < 32 * 32; i += blockDim.x) {
        int j = i >> 5, k = i & 31;
        sW2T[j * 36 + k] = W2[k * 32 + j];
    }
    if (tid < 32) { sb1[tid] = b1[tid]; sb2[tid] = b2[tid]; }
    __syncthreads();

    int w = tid >> 5, lane = tid & 31;
    int node = blockIdx.x * 8 + w;
    float eps1 = 1.0f + epsp[layer];

    // ---- aggregation via CSR gather ----
    float acc = 0.0f;
    int start = g_row[node];
    int end   = g_row[node + 1];
    for (int base = start; base < end; base += 32) {
        int nn = end - base; if (nn > 32) nn = 32;
        if (lane < nn) sE[w * 32 + lane] = g_srcs[base + lane];
        __syncwarp();
#pragma unroll 4
        for (int j = 0; j < nn; j++) {
            int s = sE[w * 32 + j];
            if (lane < KIN) acc += g_h[s * KIN + lane];
        }
        __syncwarp();
    }
    float zin = 0.0f;
    if (lane < KIN) zin = fmaf(eps1, g_h[node * KIN + lane], acc);
    if (lane < KP) sZ[w * 36 + lane] = (lane < KIN) ? zin : 0.0f;
    __syncwarp();

    // ---- matmul 1 + relu ----
    float a1 = sb1[lane];
#pragma unroll
    for (int k4 = 0; k4 < KP; k4 += 4) {
        float4 zv = *(const float4*)&sZ[w * 36 + k4];
        float4 wv = *(const float4*)&sW1T[lane * 36 + k4];
        a1 = fmaf(zv.x, wv.x, a1); a1 = fmaf(zv.y, wv.y, a1);
        a1 = fmaf(zv.z, wv.z, a1); a1 = fmaf(zv.w, wv.w, a1);
    }
    a1 = fmaxf(a1, 0.0f);
    __syncwarp();
    sZ[w * 36 + lane] = a1;
    __syncwarp();

    // ---- matmul 2 ----
    float a2 = sb2[lane];
#pragma unroll
    for (int k4 = 0; k4 < 32; k4 += 4) {
        float4 zv = *(const float4*)&sZ[w * 36 + k4];
        float4 wv = *(const float4*)&sW2T[lane * 36 + k4];
        a2 = fmaf(zv.x, wv.x, a2); a2 = fmaf(zv.y, wv.y, a2);
        a2 = fmaf(zv.z, wv.z, a2); a2 = fmaf(zv.w, wv.w, a2);
    }
    g_z[node * 32 + lane] = a2;
}

// ---------------- BN stats ----------------
__global__ void k_zero_stats() {
    int i = threadIdx.x;
    if (i < 64) g_stats[i] = 0.0;
}

__global__ void k_stats() {
    int tid    = threadIdx.x;
    int gtid   = blockIdx.x * blockDim.x + tid;
    int stride = gridDim.x * blockDim.x;
    float sum = 0.0f, sq = 0.0f;
    for (int i = gtid; i < NN * 32; i += stride) {
        float v = g_z[i];
        sum += v;
        sq  = fmaf(v, v, sq);
    }
    __shared__ float s_sum[256];
    __shared__ float s_sq[256];
    s_sum[tid] = sum;
    s_sq[tid]  = sq;
    __syncthreads();
    for (int off = 128; off >= 32; off >>= 1) {
        if (tid < off) {
            s_sum[tid] += s_sum[tid + off];
            s_sq[tid]  += s_sq[tid + off];
        }
        __syncthreads();
    }
    if (tid < 32) {
        atomicAdd(&g_stats[tid],      (double)s_sum[tid]);
        atomicAdd(&g_stats[32 + tid], (double)s_sq[tid]);
    }
}

__global__ void k_bn_apply(const float* __restrict__ gamma, const float* __restrict__ beta,
                           int layer) {
    int i = blockIdx.x * blockDim.x + threadIdx.x;
    if (i >= NN * 32) return;
    int ch   = i & 31;
    int node = i >> 5;
    float mu  = (float)(g_stats[ch] / (double)NN);
    float var = (float)(g_stats[32 + ch] / (double)NN) - mu * mu;
    float scale = gamma[ch] * rsqrtf(var + BN_EPS);
    float shift = beta[ch] - mu * scale;
    float v = fmaxf(fmaf(g_z[i], scale, shift), 0.0f);
    g_h[i] = v;
    g_xs[node * 128 + layer * 32 + ch] = v;
}

// ---------------- final linear + masked writeback ----------------
__global__ void k_final(const float* __restrict__ linW, const float* __restrict__ linb,
                        const float* __restrict__ x,
                        const int* __restrict__ nmask,
                        const int* __restrict__ emask,
                        const int* __restrict__ ondp, const int* __restrict__ oedp,
                        float* __restrict__ out) {
    __shared__ float sW[128 * 8];
    for (int i = threadIdx.x; i < 128 * 8; i += blockDim.x) sW[i] = linW[i];
    __syncthreads();

    int node = (blockIdx.x * blockDim.x + threadIdx.x) >> 5;
    int lane = threadIdx.x & 31;

    float acc[8];
#pragma unroll
    for (int o = 0; o < 8; o++) acc[o] = 0.0f;
#pragma unroll
    for (int j = 0; j < 4; j++) {
        int k = j * 32 + lane;
        float v = g_xs[node * 128 + k];
#pragma unroll
        for (int o = 0; o < 8; o++)
            acc[o] = fmaf(v, sW[k * 8 + o], acc[o]);
    }
#pragma unroll
    for (int off = 16; off > 0; off >>= 1) {
#pragma unroll
        for (int o = 0; o < 8; o++)
            acc[o] += __shfl_xor_sync(0xffffffffu, acc[o], off);
    }
    if (lane < 8) {
        int c = lane;
        float nv = acc[c] + linb[c];
        int ond = ondp[0];
        int oed = oedp[0];
        bool nm = nmask[node] != 0;
        bool em = emask[node] != 0;
        bool take = (nm && c >= 1 && c < ond + 1) || (em && c >= 1 && c < oed + 1);
        out[node * 8 + c] = take ? nv : x[node * 8 + c];
    }
}

// ---------------- launch ----------------
extern "C" void kernel_launch(void* const* d_in, const int* in_sizes, int n_in,
                              void* d_out, int out_size) {
    const float* x     = (const float*)d_in[0];
    const float* t     = (const float*)d_in[1];
    const int*   ei    = (const int*)d_in[2];
    const int*   nmask = (const int*)d_in[3];
    const int*   emask = (const int*)d_in[4];
    const int*   ondp  = (const int*)d_in[5];
    const int*   oedp  = (const int*)d_in[6];
    const float* W1f   = (const float*)d_in[7];
    const float* b1f   = (const float*)d_in[8];
    const float* W2f   = (const float*)d_in[9];
    const float* b2f   = (const float*)d_in[10];
    const float* W1r   = (const float*)d_in[11];
    const float* b1r   = (const float*)d_in[12];
    const float* W2r   = (const float*)d_in[13];
    const float* b2r   = (const float*)d_in[14];
    const float* eps   = (const float*)d_in[15];
    const float* gamma = (const float*)d_in[16];
    const float* beta  = (const float*)d_in[17];
    const float* linW  = (const float*)d_in[18];
    const float* linb  = (const float*)d_in[19];
    float*       out   = (float*)d_out;

    const int* src = ei;
    const int* dst = ei + EE;
    const int TB = 256;

    // CSR build (graph shared by all layers)
    k_zero_cnt<<<cdiv(NN, TB), TB>>>();
    k_hist<<<cdiv(EE, TB), TB>>>(dst);
    k_scan1<<<256, 1024>>>();
    k_scan2<<<1, 256>>>();
    k_scan3<<<cdiv(NN, TB), TB>>>();
    k_fill<<<cdiv(EE, TB), TB>>>(src, dst);

    k_init<<<cdiv(NN * 9, TB), TB>>>(x, t);

    for (int l = 0; l < LL; l++) {
        if (l == 0) {
            k_agg_mlp<9, 12><<<NN / 8, TB>>>(W1f, b1f, W2f, b2f, eps, 0);
        } else {
            k_agg_mlp<32, 32><<<NN / 8, TB>>>(W1r + (l - 1) * 1024, b1r + (l - 1) * 32,
                                              W2r + (l - 1) * 1024, b2r + (l - 1) * 32,
                                              eps, l);
        }
        k_zero_stats<<<1, 64>>>();
        k_stats<<<1024, 256>>>();
        k_bn_apply<<<NN * 32 / TB, TB>>>(gamma + l * 32, beta + l * 32, l);
    }

    k_final<<<NN / 8, TB>>>(linW, linb, x, nmask, emask, ondp, oedp, out);
}

// round 4
// speedup vs baseline: 3.5782x; 1.9749x over previous
#include <cuda_runtime.h>
#include <cuda_bf16.h>

#define NN 262144
#define EE 4194304
#define LL 4
#define BN_EPS 1e-5f
#define AGG_BLOCKS 2048
#define AGG_ITERS (NN / (AGG_BLOCKS * 8))   // 16

// ---------------- scratch (device globals) ----------------
__device__ float  g_h[NN * 32];     // layer input (stride 9 for layer 0, else 32)
__device__ float  g_z[NN * 32];     // pre-BN MLP output
__device__ float  g_xs[NN * 128];   // JK concat buffer
__device__ float  g_stats[LL * 64]; // per layer: [0:32) sum, [32:64) sumsq
// CSR scratch
__device__ int    g_cnt[NN];
__device__ int    g_row[NN + 1];
__device__ int    g_ofs[NN];
__device__ int    g_srcs[EE];
__device__ int    g_bsum[256];

static inline int cdiv(int a, int b) { return (a + b - 1) / b; }

// ---------------- init: h0, zero cnt, zero stats ----------------
__global__ void k_init(const float* __restrict__ x, const float* __restrict__ t) {
    int i = blockIdx.x * blockDim.x + threadIdx.x;
    if (i < NN * 9) {
        int n = i / 9;
        int c = i - n * 9;
        g_h[i] = (c < 8) ? x[n * 8 + c] : t[0];
    }
    if (i < NN) g_cnt[i] = 0;
    if (i < LL * 64) g_stats[i] = 0.0f;
}

// ---------------- CSR build ----------------
__global__ void k_hist(const int* __restrict__ dst) {
    int i = blockIdx.x * blockDim.x + threadIdx.x;
    if (i < EE) atomicAdd(&g_cnt[dst[i]], 1);
}

__global__ void k_scan1() {
    __shared__ int s[1024];
    int tid = threadIdx.x;
    int i = blockIdx.x * 1024 + tid;
    int v = g_cnt[i];
    s[tid] = v;
    __syncthreads();
    for (int off = 1; off < 1024; off <<= 1) {
        int tv = (tid >= off) ? s[tid - off] : 0;
        __syncthreads();
        s[tid] += tv;
        __syncthreads();
    }
    g_row[i] = s[tid] - v;
    if (tid == 1023) g_bsum[blockIdx.x] = s[1023];
}

__global__ void k_scan2() {
    __shared__ int s[256];
    int tid = threadIdx.x;
    int v = g_bsum[tid];
    s[tid] = v;
    __syncthreads();
    for (int off = 1; off < 256; off <<= 1) {
        int tv = (tid >= off) ? s[tid - off] : 0;
        __syncthreads();
        s[tid] += tv;
        __syncthreads();
    }
    g_bsum[tid] = s[tid] - v;
    if (tid == 0) g_row[NN] = EE;
}

__global__ void k_scan3() {
    int i = blockIdx.x * blockDim.x + threadIdx.x;
    if (i >= NN) return;
    int v = g_row[i] + g_bsum[i >> 10];
    g_row[i] = v;
    g_ofs[i] = v;
}

__global__ void k_fill(const int* __restrict__ src, const int* __restrict__ dst) {
    int i = blockIdx.x * blockDim.x + threadIdx.x;
    if (i >= EE) return;
    int pos = atomicAdd(&g_ofs[dst[i]], 1);
    g_srcs[pos] = src[i];
}

// ---------------- fused agg + MLP + BN-stats, layer 0 (KIN=9) ----------------
__global__ void k_agg_mlp9(const float* __restrict__ W1, const float* __restrict__ b1,
                           const float* __restrict__ W2, const float* __restrict__ b2,
                           const float* __restrict__ epsp) {
    __shared__ __align__(16) float sW1T[32 * 36];
    __shared__ __align__(16) float sW2T[32 * 36];
    __shared__ __align__(16) float sZ[8 * 36];
    __shared__ float sb1[32], sb2[32];
    __shared__ int   sE[8 * 32];

    int tid = threadIdx.x;
    for (int i = tid; i < 32 * 12; i += blockDim.x) {
        int j = i / 12, k = i - j * 12;
        sW1T[j * 36 + k] = (k < 9) ? W1[k * 32 + j] : 0.0f;
    }
    for (int i = tid; i < 32 * 32; i += blockDim.x) {
        int j = i >> 5, k = i & 31;
        sW2T[j * 36 + k] = W2[k * 32 + j];
    }
    if (tid < 32) { sb1[tid] = b1[tid]; sb2[tid] = b2[tid]; }
    __syncthreads();

    int w = tid >> 5, lane = tid & 31;
    float eps1 = 1.0f + epsp[0];

    float st_sum = 0.0f, st_sq = 0.0f;

    for (int it = 0; it < AGG_ITERS; it++) {
        int node = (blockIdx.x + it * AGG_BLOCKS) * 8 + w;

        float acc = 0.0f;
        int start = g_row[node];
        int end   = g_row[node + 1];
        for (int base = start; base < end; base += 32) {
            int nn = end - base; if (nn > 32) nn = 32;
            if (lane < nn) sE[w * 32 + lane] = g_srcs[base + lane];
            __syncwarp();
#pragma unroll 4
            for (int j = 0; j < nn; j++) {
                int s = sE[w * 32 + j];
                if (lane < 9) acc += g_h[s * 9 + lane];
            }
            __syncwarp();
        }
        float zin = 0.0f;
        if (lane < 9) zin = fmaf(eps1, g_h[node * 9 + lane], acc);
        if (lane < 12) sZ[w * 36 + lane] = (lane < 9) ? zin : 0.0f;
        __syncwarp();

        float a1 = sb1[lane];
#pragma unroll
        for (int k4 = 0; k4 < 12; k4 += 4) {
            float4 zv = *(const float4*)&sZ[w * 36 + k4];
            float4 wv = *(const float4*)&sW1T[lane * 36 + k4];
            a1 = fmaf(zv.x, wv.x, a1); a1 = fmaf(zv.y, wv.y, a1);
            a1 = fmaf(zv.z, wv.z, a1); a1 = fmaf(zv.w, wv.w, a1);
        }
        a1 = fmaxf(a1, 0.0f);
        __syncwarp();
        sZ[w * 36 + lane] = a1;
        __syncwarp();

        float a2 = sb2[lane];
#pragma unroll
        for (int k4 = 0; k4 < 32; k4 += 4) {
            float4 zv = *(const float4*)&sZ[w * 36 + k4];
            float4 wv = *(const float4*)&sW2T[lane * 36 + k4];
            a2 = fmaf(zv.x, wv.x, a2); a2 = fmaf(zv.y, wv.y, a2);
            a2 = fmaf(zv.z, wv.z, a2); a2 = fmaf(zv.w, wv.w, a2);
        }
        g_z[node * 32 + lane] = a2;
        st_sum += a2;
        st_sq  = fmaf(a2, a2, st_sq);
        __syncwarp();
    }

    // stats: stage per-warp, reduce across warps, 64 atomics/block
    __syncthreads();
    sW1T[w * 36 + lane] = st_sum;
    sW2T[w * 36 + lane] = st_sq;
    __syncthreads();
    if (tid < 32) {
        float s = 0.0f, q = 0.0f;
#pragma unroll
        for (int ww = 0; ww < 8; ww++) {
            s += sW1T[ww * 36 + tid];
            q += sW2T[ww * 36 + tid];
        }
        atomicAdd(&g_stats[tid], s);
        atomicAdd(&g_stats[32 + tid], q);
    }
}

// ---------------- fused agg + MLP + BN-stats, layers 1..3 (KIN=32, float4 gather) ----------------
__global__ void k_agg_mlp32(const float* __restrict__ W1, const float* __restrict__ b1,
                            const float* __restrict__ W2, const float* __restrict__ b2,
                            const float* __restrict__ epsp, int layer) {
    __shared__ __align__(16) float sW1T[32 * 36];
    __shared__ __align__(16) float sW2T[32 * 36];
    __shared__ __align__(16) float sZ[8 * 36];
    __shared__ float sb1[32], sb2[32];

    int tid = threadIdx.x;
    for (int i = tid; i < 32 * 32; i += blockDim.x) {
        int j = i >> 5, k = i & 31;
        sW1T[j * 36 + k] = W1[k * 32 + j];
        sW2T[j * 36 + k] = W2[k * 32 + j];
    }
    if (tid < 32) { sb1[tid] = b1[tid]; sb2[tid] = b2[tid]; }
    __syncthreads();

    int w = tid >> 5, lane = tid & 31;
    int q = lane & 7;        // channel group (4 ch)
    int esub = lane >> 3;    // edge sub-slot 0..3
    float eps1 = 1.0f + epsp[layer];

    float st_sum = 0.0f, st_sq = 0.0f;

    for (int it = 0; it < AGG_ITERS; it++) {
        int node = (blockIdx.x + it * AGG_BLOCKS) * 8 + w;

        float4 acc = make_float4(0.f, 0.f, 0.f, 0.f);
        int start = g_row[node];
        int end   = g_row[node + 1];
        for (int base = start; base < end; base += 32) {
            int nn = end - base; if (nn > 32) nn = 32;
            int idx = (lane < nn) ? g_srcs[base + lane] : 0;
            int iters = (nn + 3) >> 2;
            for (int jt = 0; jt < iters; jt++) {
                int e = jt * 4 + esub;
                int s = __shfl_sync(0xffffffffu, idx, e);
                if (e < nn) {
                    float4 v = *(const float4*)&g_h[s * 32 + q * 4];
                    acc.x += v.x; acc.y += v.y; acc.z += v.z; acc.w += v.w;
                }
            }
        }
        // reduce over 4 edge sub-slots (lanes q, q+8, q+16, q+24)
#pragma unroll
        for (int off = 8; off <= 16; off <<= 1) {
            acc.x += __shfl_xor_sync(0xffffffffu, acc.x, off);
            acc.y += __shfl_xor_sync(0xffffffffu, acc.y, off);
            acc.z += __shfl_xor_sync(0xffffffffu, acc.z, off);
            acc.w += __shfl_xor_sync(0xffffffffu, acc.w, off);
        }
        if (lane < 8) {
            float4 self = *(const float4*)&g_h[node * 32 + lane * 4];
            float4 z;
            z.x = fmaf(eps1, self.x, acc.x);
            z.y = fmaf(eps1, self.y, acc.y);
            z.z = fmaf(eps1, self.z, acc.z);
            z.w = fmaf(eps1, self.w, acc.w);
            *(float4*)&sZ[w * 36 + lane * 4] = z;
        }
        __syncwarp();

        float a1 = sb1[lane];
#pragma unroll
        for (int k4 = 0; k4 < 32; k4 += 4) {
            float4 zv = *(const float4*)&sZ[w * 36 + k4];
            float4 wv = *(const float4*)&sW1T[lane * 36 + k4];
            a1 = fmaf(zv.x, wv.x, a1); a1 = fmaf(zv.y, wv.y, a1);
            a1 = fmaf(zv.z, wv.z, a1); a1 = fmaf(zv.w, wv.w, a1);
        }
        a1 = fmaxf(a1, 0.0f);
        __syncwarp();
        sZ[w * 36 + lane] = a1;
        __syncwarp();

        float a2 = sb2[lane];
#pragma unroll
        for (int k4 = 0; k4 < 32; k4 += 4) {
            float4 zv = *(const float4*)&sZ[w * 36 + k4];
            float4 wv = *(const float4*)&sW2T[lane * 36 + k4];
            a2 = fmaf(zv.x, wv.x, a2); a2 = fmaf(zv.y, wv.y, a2);
            a2 = fmaf(zv.z, wv.z, a2); a2 = fmaf(zv.w, wv.w, a2);
        }
        g_z[node * 32 + lane] = a2;
        st_sum += a2;
        st_sq  = fmaf(a2, a2, st_sq);
        __syncwarp();
    }

    __syncthreads();
    sW1T[w * 36 + lane] = st_sum;
    sW2T[w * 36 + lane] = st_sq;
    __syncthreads();
    if (tid < 32) {
        float s = 0.0f, qq = 0.0f;
#pragma unroll
        for (int ww = 0; ww < 8; ww++) {
            s  += sW1T[ww * 36 + tid];
            qq += sW2T[ww * 36 + tid];
        }
        atomicAdd(&g_stats[layer * 64 + tid], s);
        atomicAdd(&g_stats[layer * 64 + 32 + tid], qq);
    }
}

// ---------------- BN apply (+ReLU), float4; writes h and xs ----------------
__global__ void k_bn_apply4(const float* __restrict__ gamma, const float* __restrict__ beta,
                            int layer) {
    int i = blockIdx.x * blockDim.x + threadIdx.x;   // over NN*8 float4 groups
    if (i >= NN * 8) return;
    int node = i >> 3;
    int c4   = (i & 7) * 4;

    float4 z = *(const float4*)&g_z[node * 32 + c4];
    float4 o;
    float inv_n = 1.0f / (float)NN;
#pragma unroll
    for (int j = 0; j < 4; j++) {
        int ch = c4 + j;
        float mu  = g_stats[layer * 64 + ch] * inv_n;
        float var = g_stats[layer * 64 + 32 + ch] * inv_n - mu * mu;
        float scale = gamma[ch] * rsqrtf(var + BN_EPS);
        float shift = beta[ch] - mu * scale;
        float v = (&z.x)[j];
        (&o.x)[j] = fmaxf(fmaf(v, scale, shift), 0.0f);
    }
    *(float4*)&g_h[node * 32 + c4] = o;
    *(float4*)&g_xs[node * 128 + layer * 32 + c4] = o;
}

// ---------------- final linear + masked writeback ----------------
__global__ void k_final(const float* __restrict__ linW, const float* __restrict__ linb,
                        const float* __restrict__ x,
                        const int* __restrict__ nmask,
                        const int* __restrict__ emask,
                        const int* __restrict__ ondp, const int* __restrict__ oedp,
                        float* __restrict__ out) {
    __shared__ float sW[128 * 8];
    for (int i = threadIdx.x; i < 128 * 8; i += blockDim.x) sW[i] = linW[i];
    __syncthreads();

    int node = (blockIdx.x * blockDim.x + threadIdx.x) >> 5;
    int lane = threadIdx.x & 31;

    float acc[8];
#pragma unroll
    for (int o = 0; o < 8; o++) acc[o] = 0.0f;
#pragma unroll
    for (int j = 0; j < 4; j++) {
        int k = j * 32 + lane;
        float v = g_xs[node * 128 + k];
#pragma unroll
        for (int o = 0; o < 8; o++)
            acc[o] = fmaf(v, sW[k * 8 + o], acc[o]);
    }
#pragma unroll
    for (int off = 16; off > 0; off >>= 1) {
#pragma unroll
        for (int o = 0; o < 8; o++)
            acc[o] += __shfl_xor_sync(0xffffffffu, acc[o], off);
    }
    if (lane < 8) {
        int c = lane;
        float nv = acc[c] + linb[c];
        int ond = ondp[0];
        int oed = oedp[0];
        bool nm = nmask[node] != 0;
        bool em = emask[node] != 0;
        bool take = (nm && c >= 1 && c < ond + 1) || (em && c >= 1 && c < oed + 1);
        out[node * 8 + c] = take ? nv : x[node * 8 + c];
    }
}

// ---------------- launch ----------------
extern "C" void kernel_launch(void* const* d_in, const int* in_sizes, int n_in,
                              void* d_out, int out_size) {
    const float* x     = (const float*)d_in[0];
    const float* t     = (const float*)d_in[1];
    const int*   ei    = (const int*)d_in[2];
    const int*   nmask = (const int*)d_in[3];
    const int*   emask = (const int*)d_in[4];
    const int*   ondp  = (const int*)d_in[5];
    const int*   oedp  = (const int*)d_in[6];
    const float* W1f   = (const float*)d_in[7];
    const float* b1f   = (const float*)d_in[8];
    const float* W2f   = (const float*)d_in[9];
    const float* b2f   = (const float*)d_in[10];
    const float* W1r   = (const float*)d_in[11];
    const float* b1r   = (const float*)d_in[12];
    const float* W2r   = (const float*)d_in[13];
    const float* b2r   = (const float*)d_in[14];
    const float* eps   = (const float*)d_in[15];
    const float* gamma = (const float*)d_in[16];
    const float* beta  = (const float*)d_in[17];
    const float* linW  = (const float*)d_in[18];
    const float* linb  = (const float*)d_in[19];
    float*       out   = (float*)d_out;

    const int* src = ei;
    const int* dst = ei + EE;
    const int TB = 256;

    k_init<<<cdiv(NN * 9, TB), TB>>>(x, t);
    k_hist<<<cdiv(EE, TB), TB>>>(dst);
    k_scan1<<<256, 1024>>>();
    k_scan2<<<1, 256>>>();
    k_scan3<<<cdiv(NN, TB), TB>>>();
    k_fill<<<cdiv(EE, TB), TB>>>(src, dst);

    for (int l = 0; l < LL; l++) {
        if (l == 0) {
            k_agg_mlp9<<<AGG_BLOCKS, TB>>>(W1f, b1f, W2f, b2f, eps);
        } else {
            k_agg_mlp32<<<AGG_BLOCKS, TB>>>(W1r + (l - 1) * 1024, b1r + (l - 1) * 32,
                                            W2r + (l - 1) * 1024, b2r + (l - 1) * 32,
                                            eps, l);
        }
        k_bn_apply4<<<cdiv(NN * 8, TB), TB>>>(gamma + l * 32, beta + l * 32, l);
    }

    k_final<<<NN / 8, TB>>>(linW, linb, x, nmask, emask, ondp, oedp, out);
}

// round 5
// speedup vs baseline: 4.1162x; 1.1504x over previous
#include <cuda_runtime.h>
#include <cuda_bf16.h>

#define NN 262144
#define EE 4194304
#define LL 4
#define BN_EPS 1e-5f
#define AGG_BLOCKS 2048
#define AGG_ITERS (NN / (AGG_BLOCKS * 8))   // 16

// ---------------- scratch (device globals) ----------------
__device__ float  g_h[NN * 32];     // layer input (stride 16 for layer 0, else 32)
__device__ float  g_z[NN * 32];     // pre-BN MLP output
__device__ float  g_out8[NN * 8];   // accumulated final projection
__device__ float  g_stats[LL * 64]; // per layer: [0:32) sum, [32:64) sumsq
// CSR scratch
__device__ int    g_cnt[NN];
__device__ int    g_row[NN + 1];
__device__ int    g_ofs[NN];
__device__ int    g_srcs[EE];
__device__ int    g_bsum[256];

static inline int cdiv(int a, int b) { return (a + b - 1) / b; }

// ---------------- init: h0 (stride 16, padded zeros), zero cnt/stats ----------------
__global__ void k_init(const float* __restrict__ x, const float* __restrict__ t) {
    int i = blockIdx.x * blockDim.x + threadIdx.x;
    if (i < NN * 16) {
        int n = i >> 4;
        int c = i & 15;
        float v = 0.0f;
        if (c < 8)       v = x[n * 8 + c];
        else if (c == 8) v = t[0];
        g_h[i] = v;
    }
    if (i < NN) g_cnt[i] = 0;
    if (i < LL * 64) g_stats[i] = 0.0f;
}

// ---------------- CSR build ----------------
__global__ void k_hist(const int* __restrict__ dst) {
    int i = blockIdx.x * blockDim.x + threadIdx.x;
    if (i < EE) atomicAdd(&g_cnt[dst[i]], 1);
}

__global__ void k_scan1() {
    __shared__ int s[1024];
    int tid = threadIdx.x;
    int i = blockIdx.x * 1024 + tid;
    int v = g_cnt[i];
    s[tid] = v;
    __syncthreads();
    for (int off = 1; off < 1024; off <<= 1) {
        int tv = (tid >= off) ? s[tid - off] : 0;
        __syncthreads();
        s[tid] += tv;
        __syncthreads();
    }
    g_row[i] = s[tid] - v;
    if (tid == 1023) g_bsum[blockIdx.x] = s[1023];
}

__global__ void k_scan2() {
    __shared__ int s[256];
    int tid = threadIdx.x;
    int v = g_bsum[tid];
    s[tid] = v;
    __syncthreads();
    for (int off = 1; off < 256; off <<= 1) {
        int tv = (tid >= off) ? s[tid - off] : 0;
        __syncthreads();
        s[tid] += tv;
        __syncthreads();
    }
    g_bsum[tid] = s[tid] - v;
    if (tid == 0) g_row[NN] = EE;
}

__global__ void k_scan3() {
    int i = blockIdx.x * blockDim.x + threadIdx.x;
    if (i >= NN) return;
    int v = g_row[i] + g_bsum[i >> 10];
    g_row[i] = v;
    g_ofs[i] = v;
}

__global__ void k_fill(const int* __restrict__ src, const int* __restrict__ dst) {
    int i = blockIdx.x * blockDim.x + threadIdx.x;
    if (i >= EE) return;
    int pos = atomicAdd(&g_ofs[dst[i]], 1);
    g_srcs[pos] = src[i];
}

// ---------------- fused agg + MLP + BN-stats, layer 0 (stride-16 h, float4 gather) ----------------
__global__ void k_agg_mlp9(const float* __restrict__ W1, const float* __restrict__ b1,
                           const float* __restrict__ W2, const float* __restrict__ b2,
                           const float* __restrict__ epsp) {
    __shared__ __align__(16) float sW1T[32 * 36];   // [j][k] k padded to 16
    __shared__ __align__(16) float sW2T[32 * 36];
    __shared__ __align__(16) float sZ[8 * 36];
    __shared__ float sb1[32], sb2[32];

    int tid = threadIdx.x;
    for (int i = tid; i < 32 * 16; i += blockDim.x) {
        int j = i >> 4, k = i & 15;
        sW1T[j * 36 + k] = (k < 9) ? W1[k * 32 + j] : 0.0f;
    }
    for (int i = tid; i < 32 * 32; i += blockDim.x) {
        int j = i >> 5, k = i & 31;
        sW2T[j * 36 + k] = W2[k * 32 + j];
    }
    if (tid < 32) { sb1[tid] = b1[tid]; sb2[tid] = b2[tid]; }
    __syncthreads();

    int w = tid >> 5, lane = tid & 31;
    int q = lane & 3;       // channel group (4 ch), 4 groups
    int esub = lane >> 2;   // edge sub-slot 0..7
    float eps1 = 1.0f + epsp[0];

    float st_sum = 0.0f, st_sq = 0.0f;

    for (int it = 0; it < AGG_ITERS; it++) {
        int node = (blockIdx.x + it * AGG_BLOCKS) * 8 + w;

        float4 acc = make_float4(0.f, 0.f, 0.f, 0.f);
        int start = g_row[node];
        int end   = g_row[node + 1];
        for (int base = start; base < end; base += 32) {
            int nn = end - base; if (nn > 32) nn = 32;
            int idx = (lane < nn) ? g_srcs[base + lane] : 0;
            if (nn == 32) {
#pragma unroll
                for (int jt = 0; jt < 4; jt++) {
                    int s = __shfl_sync(0xffffffffu, idx, jt * 8 + esub);
                    float4 v = *(const float4*)&g_h[s * 16 + q * 4];
                    acc.x += v.x; acc.y += v.y; acc.z += v.z; acc.w += v.w;
                }
            } else {
                int iters = (nn + 7) >> 3;
                for (int jt = 0; jt < iters; jt++) {
                    int e = jt * 8 + esub;
                    int s = __shfl_sync(0xffffffffu, idx, e);
                    if (e < nn) {
                        float4 v = *(const float4*)&g_h[s * 16 + q * 4];
                        acc.x += v.x; acc.y += v.y; acc.z += v.z; acc.w += v.w;
                    }
                }
            }
        }
        // reduce over 8 edge sub-slots: lanes {q, q+4, q+8, ..., q+28}
#pragma unroll
        for (int off = 4; off <= 16; off <<= 1) {
            acc.x += __shfl_xor_sync(0xffffffffu, acc.x, off);
            acc.y += __shfl_xor_sync(0xffffffffu, acc.y, off);
            acc.z += __shfl_xor_sync(0xffffffffu, acc.z, off);
            acc.w += __shfl_xor_sync(0xffffffffu, acc.w, off);
        }
        if (lane < 4) {
            float4 self = *(const float4*)&g_h[node * 16 + lane * 4];
            float4 z;
            z.x = fmaf(eps1, self.x, acc.x);
            z.y = fmaf(eps1, self.y, acc.y);
            z.z = fmaf(eps1, self.z, acc.z);
            z.w = fmaf(eps1, self.w, acc.w);
            *(float4*)&sZ[w * 36 + lane * 4] = z;
        }
        __syncwarp();

        float a1 = sb1[lane];
#pragma unroll
        for (int k4 = 0; k4 < 16; k4 += 4) {
            float4 zv = *(const float4*)&sZ[w * 36 + k4];
            float4 wv = *(const float4*)&sW1T[lane * 36 + k4];
            a1 = fmaf(zv.x, wv.x, a1); a1 = fmaf(zv.y, wv.y, a1);
            a1 = fmaf(zv.z, wv.z, a1); a1 = fmaf(zv.w, wv.w, a1);
        }
        a1 = fmaxf(a1, 0.0f);
        __syncwarp();
        sZ[w * 36 + lane] = a1;
        __syncwarp();

        float a2 = sb2[lane];
#pragma unroll
        for (int k4 = 0; k4 < 32; k4 += 4) {
            float4 zv = *(const float4*)&sZ[w * 36 + k4];
            float4 wv = *(const float4*)&sW2T[lane * 36 + k4];
            a2 = fmaf(zv.x, wv.x, a2); a2 = fmaf(zv.y, wv.y, a2);
            a2 = fmaf(zv.z, wv.z, a2); a2 = fmaf(zv.w, wv.w, a2);
        }
        g_z[node * 32 + lane] = a2;
        st_sum += a2;
        st_sq  = fmaf(a2, a2, st_sq);
        __syncwarp();
    }

    __syncthreads();
    sW1T[w * 36 + lane] = st_sum;
    sW2T[w * 36 + lane] = st_sq;
    __syncthreads();
    if (tid < 32) {
        float s = 0.0f, qq = 0.0f;
#pragma unroll
        for (int ww = 0; ww < 8; ww++) {
            s  += sW1T[ww * 36 + tid];
            qq += sW2T[ww * 36 + tid];
        }
        atomicAdd(&g_stats[tid], s);
        atomicAdd(&g_stats[32 + tid], qq);
    }
}

// ---------------- fused agg + MLP + BN-stats, layers 1..3 (KIN=32, float4 gather) ----------------
__global__ void k_agg_mlp32(const float* __restrict__ W1, const float* __restrict__ b1,
                            const float* __restrict__ W2, const float* __restrict__ b2,
                            const float* __restrict__ epsp, int layer) {
    __shared__ __align__(16) float sW1T[32 * 36];
    __shared__ __align__(16) float sW2T[32 * 36];
    __shared__ __align__(16) float sZ[8 * 36];
    __shared__ float sb1[32], sb2[32];

    int tid = threadIdx.x;
    for (int i = tid; i < 32 * 32; i += blockDim.x) {
        int j = i >> 5, k = i & 31;
        sW1T[j * 36 + k] = W1[k * 32 + j];
        sW2T[j * 36 + k] = W2[k * 32 + j];
    }
    if (tid < 32) { sb1[tid] = b1[tid]; sb2[tid] = b2[tid]; }
    __syncthreads();

    int w = tid >> 5, lane = tid & 31;
    int q = lane & 7;        // channel group (4 ch)
    int esub = lane >> 3;    // edge sub-slot 0..3
    float eps1 = 1.0f + epsp[layer];

    float st_sum = 0.0f, st_sq = 0.0f;

    for (int it = 0; it < AGG_ITERS; it++) {
        int node = (blockIdx.x + it * AGG_BLOCKS) * 8 + w;

        float4 acc = make_float4(0.f, 0.f, 0.f, 0.f);
        int start = g_row[node];
        int end   = g_row[node + 1];
        for (int base = start; base < end; base += 32) {
            int nn = end - base; if (nn > 32) nn = 32;
            int idx = (lane < nn) ? g_srcs[base + lane] : 0;
            if (nn == 32) {
#pragma unroll
                for (int jt = 0; jt < 8; jt++) {
                    int s = __shfl_sync(0xffffffffu, idx, jt * 4 + esub);
                    float4 v = *(const float4*)&g_h[s * 32 + q * 4];
                    acc.x += v.x; acc.y += v.y; acc.z += v.z; acc.w += v.w;
                }
            } else {
                int iters = (nn + 3) >> 2;
                for (int jt = 0; jt < iters; jt++) {
                    int e = jt * 4 + esub;
                    int s = __shfl_sync(0xffffffffu, idx, e);
                    if (e < nn) {
                        float4 v = *(const float4*)&g_h[s * 32 + q * 4];
                        acc.x += v.x; acc.y += v.y; acc.z += v.z; acc.w += v.w;
                    }
                }
            }
        }
#pragma unroll
        for (int off = 8; off <= 16; off <<= 1) {
            acc.x += __shfl_xor_sync(0xffffffffu, acc.x, off);
            acc.y += __shfl_xor_sync(0xffffffffu, acc.y, off);
            acc.z += __shfl_xor_sync(0xffffffffu, acc.z, off);
            acc.w += __shfl_xor_sync(0xffffffffu, acc.w, off);
        }
        if (lane < 8) {
            float4 self = *(const float4*)&g_h[node * 32 + lane * 4];
            float4 z;
            z.x = fmaf(eps1, self.x, acc.x);
            z.y = fmaf(eps1, self.y, acc.y);
            z.z = fmaf(eps1, self.z, acc.z);
            z.w = fmaf(eps1, self.w, acc.w);
            *(float4*)&sZ[w * 36 + lane * 4] = z;
        }
        __syncwarp();

        float a1 = sb1[lane];
#pragma unroll
        for (int k4 = 0; k4 < 32; k4 += 4) {
            float4 zv = *(const float4*)&sZ[w * 36 + k4];
            float4 wv = *(const float4*)&sW1T[lane * 36 + k4];
            a1 = fmaf(zv.x, wv.x, a1); a1 = fmaf(zv.y, wv.y, a1);
            a1 = fmaf(zv.z, wv.z, a1); a1 = fmaf(zv.w, wv.w, a1);
        }
        a1 = fmaxf(a1, 0.0f);
        __syncwarp();
        sZ[w * 36 + lane] = a1;
        __syncwarp();

        float a2 = sb2[lane];
#pragma unroll
        for (int k4 = 0; k4 < 32; k4 += 4) {
            float4 zv = *(const float4*)&sZ[w * 36 + k4];
            float4 wv = *(const float4*)&sW2T[lane * 36 + k4];
            a2 = fmaf(zv.x, wv.x, a2); a2 = fmaf(zv.y, wv.y, a2);
            a2 = fmaf(zv.z, wv.z, a2); a2 = fmaf(zv.w, wv.w, a2);
        }
        g_z[node * 32 + lane] = a2;
        st_sum += a2;
        st_sq  = fmaf(a2, a2, st_sq);
        __syncwarp();
    }

    __syncthreads();
    sW1T[w * 36 + lane] = st_sum;
    sW2T[w * 36 + lane] = st_sq;
    __syncthreads();
    if (tid < 32) {
        float s = 0.0f, qq = 0.0f;
#pragma unroll
        for (int ww = 0; ww < 8; ww++) {
            s  += sW1T[ww * 36 + tid];
            qq += sW2T[ww * 36 + tid];
        }
        atomicAdd(&g_stats[layer * 64 + tid], s);
        atomicAdd(&g_stats[layer * 64 + 32 + tid], qq);
    }
}

// ---------------- BN apply (+ReLU) + per-layer projection into g_out8 ----------------
// block = 256 threads, 32 nodes. Writes g_h (stride 32) and accumulates out8.
__global__ void k_bn_proj(const float* __restrict__ gamma, const float* __restrict__ beta,
                          const float* __restrict__ linW, int layer) {
    __shared__ float sV[32 * 33];    // BN'd values [node][ch]
    __shared__ float sW[32 * 8];     // linW slice [ch][o]
    __shared__ float sScale[32], sShift[32];

    int tid = threadIdx.x;
    int node0 = blockIdx.x * 32;

    sW[tid] = linW[layer * 32 * 8 + tid];   // rows layer*32..+32 of [128][8]
    if (tid < 32) {
        float inv_n = 1.0f / (float)NN;
        float mu  = g_stats[layer * 64 + tid] * inv_n;
        float var = g_stats[layer * 64 + 32 + tid] * inv_n - mu * mu;
        float scale = gamma[tid] * rsqrtf(var + BN_EPS);
        sScale[tid] = scale;
        sShift[tid] = beta[tid] - mu * scale;
    }
    __syncthreads();

    // stage + BN + write h (coalesced)
#pragma unroll
    for (int r = 0; r < 4; r++) {
        int idx  = r * 256 + tid;          // 0..1023
        int node = idx >> 5;
        int ch   = idx & 31;
        float v = g_z[(node0 + node) * 32 + ch];
        float b = fmaxf(fmaf(v, sScale[ch], sShift[ch]), 0.0f);
        g_h[(node0 + node) * 32 + ch] = b;
        sV[node * 33 + ch] = b;
    }
    __syncthreads();

    // projection: thread -> (node, o)
    int node = tid >> 3;
    int o    = tid & 7;
    float acc = 0.0f;
#pragma unroll
    for (int k = 0; k < 32; k++)
        acc = fmaf(sV[node * 33 + k], sW[k * 8 + o], acc);

    int gi = node0 * 8 + tid;   // == (node0+node)*8 + o
    if (layer == 0) g_out8[gi] = acc;
    else            g_out8[gi] += acc;
}

// ---------------- final masked writeback ----------------
__global__ void k_final(const float* __restrict__ linb,
                        const float* __restrict__ x,
                        const int* __restrict__ nmask,
                        const int* __restrict__ emask,
                        const int* __restrict__ ondp, const int* __restrict__ oedp,
                        float* __restrict__ out) {
    int i = blockIdx.x * blockDim.x + threadIdx.x;
    if (i >= NN * 8) return;
    int node = i >> 3;
    int c    = i & 7;
    float nv = g_out8[i] + linb[c];
    int ond = ondp[0];
    int oed = oedp[0];
    bool nm = nmask[node] != 0;
    bool em = emask[node] != 0;
    bool take = (nm && c >= 1 && c < ond + 1) || (em && c >= 1 && c < oed + 1);
    out[i] = take ? nv : x[i];
}

// ---------------- launch ----------------
extern "C" void kernel_launch(void* const* d_in, const int* in_sizes, int n_in,
                              void* d_out, int out_size) {
    const float* x     = (const float*)d_in[0];
    const float* t     = (const float*)d_in[1];
    const int*   ei    = (const int*)d_in[2];
    const int*   nmask = (const int*)d_in[3];
    const int*   emask = (const int*)d_in[4];
    const int*   ondp  = (const int*)d_in[5];
    const int*   oedp  = (const int*)d_in[6];
    const float* W1f   = (const float*)d_in[7];
    const float* b1f   = (const float*)d_in[8];
    const float* W2f   = (const float*)d_in[9];
    const float* b2f   = (const float*)d_in[10];
    const float* W1r   = (const float*)d_in[11];
    const float* b1r   = (const float*)d_in[12];
    const float* W2r   = (const float*)d_in[13];
    const float* b2r   = (const float*)d_in[14];
    const float* eps   = (const float*)d_in[15];
    const float* gamma = (const float*)d_in[16];
    const float* beta  = (const float*)d_in[17];
    const float* linW  = (const float*)d_in[18];
    const float* linb  = (const float*)d_in[19];
    float*       out   = (float*)d_out;

    const int* src = ei;
    const int* dst = ei + EE;
    const int TB = 256;

    k_init<<<cdiv(NN * 16, TB), TB>>>(x, t);
    k_hist<<<cdiv(EE, TB), TB>>>(dst);
    k_scan1<<<256, 1024>>>();
    k_scan2<<<1, 256>>>();
    k_scan3<<<cdiv(NN, TB), TB>>>();
    k_fill<<<cdiv(EE, TB), TB>>>(src, dst);

    for (int l = 0; l < LL; l++) {
        if (l == 0) {
            k_agg_mlp9<<<AGG_BLOCKS, TB>>>(W1f, b1f, W2f, b2f, eps);
        } else {
            k_agg_mlp32<<<AGG_BLOCKS, TB>>>(W1r + (l - 1) * 1024, b1r + (l - 1) * 32,
                                            W2r + (l - 1) * 1024, b2r + (l - 1) * 32,
                                            eps, l);
        }
        k_bn_proj<<<NN / 32, TB>>>(gamma + l * 32, beta + l * 32, linW, l);
    }

    k_final<<<cdiv(NN * 8, TB), TB>>>(linb, x, nmask, emask, ondp, oedp, out);
}

// round 9
// speedup vs baseline: 4.5867x; 1.1143x over previous
#include <cuda_runtime.h>
#include <cuda_bf16.h>

#define NN 262144
#define EE 4194304
#define LL 4
#define BN_EPS 1e-5f
#define AGG_BLOCKS 2048
#define AGG_PAIRS 8   // each warp handles 2 nodes per outer iter; 8 iters * 2 * 8 warps * 2048 blocks = NN

// ---------------- scratch (device globals; zero-initialized at module load,
// re-zeroed at tail of k_final each call so every invocation sees zeros) -----
__device__ float  g_h[NN * 32];     // layer input (stride 16 for layer 0, else 32)
__device__ float  g_z[NN * 32];     // pre-BN MLP output
__device__ float  g_out8[NN * 8];   // accumulated final projection
__device__ float  g_stats[LL * 64]; // per layer: [0:32) sum, [32:64) sumsq
__device__ int    g_cnt[NN];
__device__ int    g_row[NN + 1];
__device__ int    g_ofs[NN];
__device__ int    g_srcs[EE];
__device__ int    g_bsum[256];

static inline int cdiv(int a, int b) { return (a + b - 1) / b; }

// ---------------- init h0 (stride 16, zero-padded) + degree histogram ----------------
// NN*16 == EE, so one grid serves both. g_cnt is pre-zeroed (module load / k_final tail).
__global__ void k_init_hist(const float* __restrict__ x, const float* __restrict__ t,
                            const int* __restrict__ dst) {
    int i = blockIdx.x * blockDim.x + threadIdx.x;
    if (i < NN * 16) {
        int n = i >> 4;
        int c = i & 15;
        float v = 0.0f;
        if (c < 8)       v = x[n * 8 + c];
        else if (c == 8) v = t[0];
        g_h[i] = v;
    }
    if (i < EE) atomicAdd(&g_cnt[dst[i]], 1);
}

// ---------------- CSR scan ----------------
__global__ void k_scan1() {
    __shared__ int s[1024];
    int tid = threadIdx.x;
    int i = blockIdx.x * 1024 + tid;
    int v = g_cnt[i];
    s[tid] = v;
    __syncthreads();
    for (int off = 1; off < 1024; off <<= 1) {
        int tv = (tid >= off) ? s[tid - off] : 0;
        __syncthreads();
        s[tid] += tv;
        __syncthreads();
    }
    g_row[i] = s[tid] - v;
    if (tid == 1023) g_bsum[blockIdx.x] = s[1023];
}

__global__ void k_scan2() {
    __shared__ int s[256];
    int tid = threadIdx.x;
    int v = g_bsum[tid];
    s[tid] = v;
    __syncthreads();
    for (int off = 1; off < 256; off <<= 1) {
        int tv = (tid >= off) ? s[tid - off] : 0;
        __syncthreads();
        s[tid] += tv;
        __syncthreads();
    }
    g_bsum[tid] = s[tid] - v;
    if (tid == 0) g_row[NN] = EE;
}

__global__ void k_scan3() {
    int i = blockIdx.x * blockDim.x + threadIdx.x;
    if (i >= NN) return;
    int v = g_row[i] + g_bsum[i >> 10];
    g_row[i] = v;
    g_ofs[i] = v;
}

__global__ void k_fill(const int* __restrict__ src, const int* __restrict__ dst) {
    int i = blockIdx.x * blockDim.x + threadIdx.x;
    if (i >= EE) return;
    int pos = atomicAdd(&g_ofs[dst[i]], 1);
    g_srcs[pos] = src[i];
}

// ---------------- fused agg + MLP + BN-stats, layer 0 (stride-16 h) ----------------
// 2 nodes per warp per outer iter; branch-free predicated first-chunk gather.
__global__ void k_agg_mlp9(const float* __restrict__ W1, const float* __restrict__ b1,
                           const float* __restrict__ W2, const float* __restrict__ b2,
                           const float* __restrict__ epsp) {
    __shared__ __align__(16) float sW1T[32 * 36];
    __shared__ __align__(16) float sW2T[32 * 36];
    __shared__ __align__(16) float sZ[16 * 36];
    __shared__ float sb1[32], sb2[32];

    int tid = threadIdx.x;
    for (int i = tid; i < 32 * 16; i += blockDim.x) {
        int j = i >> 4, k = i & 15;
        sW1T[j * 36 + k] = (k < 9) ? W1[k * 32 + j] : 0.0f;
    }
    for (int i = tid; i < 32 * 32; i += blockDim.x) {
        int j = i >> 5, k = i & 31;
        sW2T[j * 36 + k] = W2[k * 32 + j];
    }
    if (tid < 32) { sb1[tid] = b1[tid]; sb2[tid] = b2[tid]; }
    __syncthreads();

    int w = tid >> 5, lane = tid & 31;
    int q = lane & 3;       // channel group (4 ch)
    int esub = lane >> 2;   // edge sub-slot 0..7
    float eps1 = 1.0f + epsp[0];

    float st_sum = 0.0f, st_sq = 0.0f;

    for (int it = 0; it < AGG_PAIRS; it++) {
        int nodeA = (blockIdx.x + it * AGG_BLOCKS) * 8 + w;
        int nodeB = nodeA + NN / 2;

        int sA = g_row[nodeA], eA = g_row[nodeA + 1];
        int sB = g_row[nodeB], eB = g_row[nodeB + 1];
        int nnA = eA - sA; if (nnA > 32) nnA = 32;
        int nnB = eB - sB; if (nnB > 32) nnB = 32;
        int idxA = (lane < nnA) ? g_srcs[sA + lane] : 0;
        int idxB = (lane < nnB) ? g_srcs[sB + lane] : 0;

        float4 accA = make_float4(0.f, 0.f, 0.f, 0.f);
        float4 accB = make_float4(0.f, 0.f, 0.f, 0.f);

#pragma unroll
        for (int jt = 0; jt < 4; jt++) {
            int e = jt * 8 + esub;
            int sa = __shfl_sync(0xffffffffu, idxA, e);
            if (e < nnA) {
                float4 v = *(const float4*)&g_h[sa * 16 + q * 4];
                accA.x += v.x; accA.y += v.y; accA.z += v.z; accA.w += v.w;
            }
        }
#pragma unroll
        for (int jt = 0; jt < 4; jt++) {
            int e = jt * 8 + esub;
            int sb = __shfl_sync(0xffffffffu, idxB, e);
            if (e < nnB) {
                float4 v = *(const float4*)&g_h[sb * 16 + q * 4];
                accB.x += v.x; accB.y += v.y; accB.z += v.z; accB.w += v.w;
            }
        }
        // rare extra chunks (deg > 32)
        for (int base = sA + 32; base < eA; base += 32) {
            int nn = eA - base; if (nn > 32) nn = 32;
            int idx = (lane < nn) ? g_srcs[base + lane] : 0;
#pragma unroll
            for (int jt = 0; jt < 4; jt++) {
                int e = jt * 8 + esub;
                int s = __shfl_sync(0xffffffffu, idx, e);
                if (e < nn) {
                    float4 v = *(const float4*)&g_h[s * 16 + q * 4];
                    accA.x += v.x; accA.y += v.y; accA.z += v.z; accA.w += v.w;
                }
            }
        }
        for (int base = sB + 32; base < eB; base += 32) {
            int nn = eB - base; if (nn > 32) nn = 32;
            int idx = (lane < nn) ? g_srcs[base + lane] : 0;
#pragma unroll
            for (int jt = 0; jt < 4; jt++) {
                int e = jt * 8 + esub;
                int s = __shfl_sync(0xffffffffu, idx, e);
                if (e < nn) {
                    float4 v = *(const float4*)&g_h[s * 16 + q * 4];
                    accB.x += v.x; accB.y += v.y; accB.z += v.z; accB.w += v.w;
                }
            }
        }

        // reduce 8 edge sub-slots
#pragma unroll
        for (int off = 4; off <= 16; off <<= 1) {
            accA.x += __shfl_xor_sync(0xffffffffu, accA.x, off);
            accA.y += __shfl_xor_sync(0xffffffffu, accA.y, off);
            accA.z += __shfl_xor_sync(0xffffffffu, accA.z, off);
            accA.w += __shfl_xor_sync(0xffffffffu, accA.w, off);
            accB.x += __shfl_xor_sync(0xffffffffu, accB.x, off);
            accB.y += __shfl_xor_sync(0xffffffffu, accB.y, off);
            accB.z += __shfl_xor_sync(0xffffffffu, accB.z, off);
            accB.w += __shfl_xor_sync(0xffffffffu, accB.w, off);
        }
        if (lane < 4) {
            float4 selfA = *(const float4*)&g_h[nodeA * 16 + lane * 4];
            float4 zA;
            zA.x = fmaf(eps1, selfA.x, accA.x);
            zA.y = fmaf(eps1, selfA.y, accA.y);
            zA.z = fmaf(eps1, selfA.z, accA.z);
            zA.w = fmaf(eps1, selfA.w, accA.w);
            *(float4*)&sZ[w * 36 + lane * 4] = zA;
            float4 selfB = *(const float4*)&g_h[nodeB * 16 + lane * 4];
            float4 zB;
            zB.x = fmaf(eps1, selfB.x, accB.x);
            zB.y = fmaf(eps1, selfB.y, accB.y);
            zB.z = fmaf(eps1, selfB.z, accB.z);
            zB.w = fmaf(eps1, selfB.w, accB.w);
            *(float4*)&sZ[(w + 8) * 36 + lane * 4] = zB;
        }
        __syncwarp();

        // MLP A
        float a1 = sb1[lane];
#pragma unroll
        for (int k4 = 0; k4 < 16; k4 += 4) {
            float4 zv = *(const float4*)&sZ[w * 36 + k4];
            float4 wv = *(const float4*)&sW1T[lane * 36 + k4];
            a1 = fmaf(zv.x, wv.x, a1); a1 = fmaf(zv.y, wv.y, a1);
            a1 = fmaf(zv.z, wv.z, a1); a1 = fmaf(zv.w, wv.w, a1);
        }
        // MLP B stage 1
        float b1v = sb1[lane];
#pragma unroll
        for (int k4 = 0; k4 < 16; k4 += 4) {
            float4 zv = *(const float4*)&sZ[(w + 8) * 36 + k4];
            float4 wv = *(const float4*)&sW1T[lane * 36 + k4];
            b1v = fmaf(zv.x, wv.x, b1v); b1v = fmaf(zv.y, wv.y, b1v);
            b1v = fmaf(zv.z, wv.z, b1v); b1v = fmaf(zv.w, wv.w, b1v);
        }
        a1  = fmaxf(a1, 0.0f);
        b1v = fmaxf(b1v, 0.0f);
        __syncwarp();
        sZ[w * 36 + lane] = a1;
        sZ[(w + 8) * 36 + lane] = b1v;
        __syncwarp();

        float a2 = sb2[lane];
        float b2v = sb2[lane];
#pragma unroll
        for (int k4 = 0; k4 < 32; k4 += 4) {
            float4 zvA = *(const float4*)&sZ[w * 36 + k4];
            float4 zvB = *(const float4*)&sZ[(w + 8) * 36 + k4];
            float4 wv  = *(const float4*)&sW2T[lane * 36 + k4];
            a2  = fmaf(zvA.x, wv.x, a2);  a2  = fmaf(zvA.y, wv.y, a2);
            a2  = fmaf(zvA.z, wv.z, a2);  a2  = fmaf(zvA.w, wv.w, a2);
            b2v = fmaf(zvB.x, wv.x, b2v); b2v = fmaf(zvB.y, wv.y, b2v);
            b2v = fmaf(zvB.z, wv.z, b2v); b2v = fmaf(zvB.w, wv.w, b2v);
        }
        g_z[nodeA * 32 + lane] = a2;
        g_z[nodeB * 32 + lane] = b2v;
        st_sum += a2 + b2v;
        st_sq  = fmaf(a2, a2, st_sq);
        st_sq  = fmaf(b2v, b2v, st_sq);
        __syncwarp();
    }

    __syncthreads();
    sW1T[w * 36 + lane] = st_sum;
    sW2T[w * 36 + lane] = st_sq;
    __syncthreads();
    if (tid < 32) {
        float s = 0.0f, qq = 0.0f;
#pragma unroll
        for (int ww = 0; ww < 8; ww++) {
            s  += sW1T[ww * 36 + tid];
            qq += sW2T[ww * 36 + tid];
        }
        atomicAdd(&g_stats[tid], s);
        atomicAdd(&g_stats[32 + tid], qq);
    }
}

// ---------------- fused agg + MLP + BN-stats, layers 1..3 (KIN=32) ----------------
__global__ void k_agg_mlp32(const float* __restrict__ W1, const float* __restrict__ b1,
                            const float* __restrict__ W2, const float* __restrict__ b2,
                            const float* __restrict__ epsp, int layer) {
    __shared__ __align__(16) float sW1T[32 * 36];
    __shared__ __align__(16) float sW2T[32 * 36];
    __shared__ __align__(16) float sZ[16 * 36];
    __shared__ float sb1[32], sb2[32];

    int tid = threadIdx.x;
    for (int i = tid; i < 32 * 32; i += blockDim.x) {
        int j = i >> 5, k = i & 31;
        sW1T[j * 36 + k] = W1[k * 32 + j];
        sW2T[j * 36 + k] = W2[k * 32 + j];
    }
    if (tid < 32) { sb1[tid] = b1[tid]; sb2[tid] = b2[tid]; }
    __syncthreads();

    int w = tid >> 5, lane = tid & 31;
    int q = lane & 7;        // channel group (4 ch)
    int esub = lane >> 3;    // edge sub-slot 0..3
    float eps1 = 1.0f + epsp[layer];

    float st_sum = 0.0f, st_sq = 0.0f;

    for (int it = 0; it < AGG_PAIRS; it++) {
        int nodeA = (blockIdx.x + it * AGG_BLOCKS) * 8 + w;
        int nodeB = nodeA + NN / 2;

        int sA = g_row[nodeA], eA = g_row[nodeA + 1];
        int sB = g_row[nodeB], eB = g_row[nodeB + 1];
        int nnA = eA - sA; if (nnA > 32) nnA = 32;
        int nnB = eB - sB; if (nnB > 32) nnB = 32;
        int idxA = (lane < nnA) ? g_srcs[sA + lane] : 0;
        int idxB = (lane < nnB) ? g_srcs[sB + lane] : 0;

        float4 accA = make_float4(0.f, 0.f, 0.f, 0.f);
        float4 accB = make_float4(0.f, 0.f, 0.f, 0.f);

#pragma unroll
        for (int jt = 0; jt < 8; jt++) {
            int e = jt * 4 + esub;
            int sa = __shfl_sync(0xffffffffu, idxA, e);
            if (e < nnA) {
                float4 v = *(const float4*)&g_h[sa * 32 + q * 4];
                accA.x += v.x; accA.y += v.y; accA.z += v.z; accA.w += v.w;
            }
        }
#pragma unroll
        for (int jt = 0; jt < 8; jt++) {
            int e = jt * 4 + esub;
            int sb = __shfl_sync(0xffffffffu, idxB, e);
            if (e < nnB) {
                float4 v = *(const float4*)&g_h[sb * 32 + q * 4];
                accB.x += v.x; accB.y += v.y; accB.z += v.z; accB.w += v.w;
            }
        }
        for (int base = sA + 32; base < eA; base += 32) {
            int nn = eA - base; if (nn > 32) nn = 32;
            int idx = (lane < nn) ? g_srcs[base + lane] : 0;
#pragma unroll
            for (int jt = 0; jt < 8; jt++) {
                int e = jt * 4 + esub;
                int s = __shfl_sync(0xffffffffu, idx, e);
                if (e < nn) {
                    float4 v = *(const float4*)&g_h[s * 32 + q * 4];
                    accA.x += v.x; accA.y += v.y; accA.z += v.z; accA.w += v.w;
                }
            }
        }
        for (int base = sB + 32; base < eB; base += 32) {
            int nn = eB - base; if (nn > 32) nn = 32;
            int idx = (lane < nn) ? g_srcs[base + lane] : 0;
#pragma unroll
            for (int jt = 0; jt < 8; jt++) {
                int e = jt * 4 + esub;
                int s = __shfl_sync(0xffffffffu, idx, e);
                if (e < nn) {
                    float4 v = *(const float4*)&g_h[s * 32 + q * 4];
                    accB.x += v.x; accB.y += v.y; accB.z += v.z; accB.w += v.w;
                }
            }
        }

#pragma unroll
        for (int off = 8; off <= 16; off <<= 1) {
            accA.x += __shfl_xor_sync(0xffffffffu, accA.x, off);
            accA.y += __shfl_xor_sync(0xffffffffu, accA.y, off);
            accA.z += __shfl_xor_sync(0xffffffffu, accA.z, off);
            accA.w += __shfl_xor_sync(0xffffffffu, accA.w, off);
            accB.x += __shfl_xor_sync(0xffffffffu, accB.x, off);
            accB.y += __shfl_xor_sync(0xffffffffu, accB.y, off);
            accB.z += __shfl_xor_sync(0xffffffffu, accB.z, off);
            accB.w += __shfl_xor_sync(0xffffffffu, accB.w, off);
        }
        if (lane < 8) {
            float4 selfA = *(const float4*)&g_h[nodeA * 32 + lane * 4];
            float4 zA;
            zA.x = fmaf(eps1, selfA.x, accA.x);
            zA.y = fmaf(eps1, selfA.y, accA.y);
            zA.z = fmaf(eps1, selfA.z, accA.z);
            zA.w = fmaf(eps1, selfA.w, accA.w);
            *(float4*)&sZ[w * 36 + lane * 4] = zA;
            float4 selfB = *(const float4*)&g_h[nodeB * 32 + lane * 4];
            float4 zB;
            zB.x = fmaf(eps1, selfB.x, accB.x);
            zB.y = fmaf(eps1, selfB.y, accB.y);
            zB.z = fmaf(eps1, selfB.z, accB.z);
            zB.w = fmaf(eps1, selfB.w, accB.w);
            *(float4*)&sZ[(w + 8) * 36 + lane * 4] = zB;
        }
        __syncwarp();

        float a1 = sb1[lane];
        float b1v = sb1[lane];
#pragma unroll
        for (int k4 = 0; k4 < 32; k4 += 4) {
            float4 zvA = *(const float4*)&sZ[w * 36 + k4];
            float4 zvB = *(const float4*)&sZ[(w + 8) * 36 + k4];
            float4 wv  = *(const float4*)&sW1T[lane * 36 + k4];
            a1  = fmaf(zvA.x, wv.x, a1);  a1  = fmaf(zvA.y, wv.y, a1);
            a1  = fmaf(zvA.z, wv.z, a1);  a1  = fmaf(zvA.w, wv.w, a1);
            b1v = fmaf(zvB.x, wv.x, b1v); b1v = fmaf(zvB.y, wv.y, b1v);
            b1v = fmaf(zvB.z, wv.z, b1v); b1v = fmaf(zvB.w, wv.w, b1v);
        }
        a1  = fmaxf(a1, 0.0f);
        b1v = fmaxf(b1v, 0.0f);
        __syncwarp();
        sZ[w * 36 + lane] = a1;
        sZ[(w + 8) * 36 + lane] = b1v;
        __syncwarp();

        float a2 = sb2[lane];
        float b2v = sb2[lane];
#pragma unroll
        for (int k4 = 0; k4 < 32; k4 += 4) {
            float4 zvA = *(const float4*)&sZ[w * 36 + k4];
            float4 zvB = *(const float4*)&sZ[(w + 8) * 36 + k4];
            float4 wv  = *(const float4*)&sW2T[lane * 36 + k4];
            a2  = fmaf(zvA.x, wv.x, a2);  a2  = fmaf(zvA.y, wv.y, a2);
            a2  = fmaf(zvA.z, wv.z, a2);  a2  = fmaf(zvA.w, wv.w, a2);
            b2v = fmaf(zvB.x, wv.x, b2v); b2v = fmaf(zvB.y, wv.y, b2v);
            b2v = fmaf(zvB.z, wv.z, b2v); b2v = fmaf(zvB.w, wv.w, b2v);
        }
        g_z[nodeA * 32 + lane] = a2;
        g_z[nodeB * 32 + lane] = b2v;
        st_sum += a2 + b2v;
        st_sq  = fmaf(a2, a2, st_sq);
        st_sq  = fmaf(b2v, b2v, st_sq);
        __syncwarp();
    }

    __syncthreads();
    sW1T[w * 36 + lane] = st_sum;
    sW2T[w * 36 + lane] = st_sq;
    __syncthreads();
    if (tid < 32) {
        float s = 0.0f, qq = 0.0f;
#pragma unroll
        for (int ww = 0; ww < 8; ww++) {
            s  += sW1T[ww * 36 + tid];
            qq += sW2T[ww * 36 + tid];
        }
        atomicAdd(&g_stats[layer * 64 + tid], s);
        atomicAdd(&g_stats[layer * 64 + 32 + tid], qq);
    }
}

// ---------------- BN apply (+ReLU) + per-layer projection into g_out8 ----------------
__global__ void k_bn_proj(const float* __restrict__ gamma, const float* __restrict__ beta,
                          const float* __restrict__ linW, int layer) {
    __shared__ float sV[32 * 33];
    __shared__ float sW[32 * 8];
    __shared__ float sScale[32], sShift[32];

    int tid = threadIdx.x;
    int node0 = blockIdx.x * 32;

    sW[tid] = linW[layer * 32 * 8 + tid];
    if (tid < 32) {
        float inv_n = 1.0f / (float)NN;
        float mu  = g_stats[layer * 64 + tid] * inv_n;
        float var = g_stats[layer * 64 + 32 + tid] * inv_n - mu * mu;
        float scale = gamma[tid] * rsqrtf(var + BN_EPS);
        sScale[tid] = scale;
        sShift[tid] = beta[tid] - mu * scale;
    }
    __syncthreads();

#pragma unroll
    for (int r = 0; r < 4; r++) {
        int idx  = r * 256 + tid;
        int node = idx >> 5;
        int ch   = idx & 31;
        float v = g_z[(node0 + node) * 32 + ch];
        float b = fmaxf(fmaf(v, sScale[ch], sShift[ch]), 0.0f);
        g_h[(node0 + node) * 32 + ch] = b;
        sV[node * 33 + ch] = b;
    }
    __syncthreads();

    int node = tid >> 3;
    int o    = tid & 7;
    float acc = 0.0f;
#pragma unroll
    for (int k = 0; k < 32; k++)
        acc = fmaf(sV[node * 33 + k], sW[k * 8 + o], acc);

    int gi = node0 * 8 + tid;
    if (layer == 0) g_out8[gi] = acc;
    else            g_out8[gi] += acc;
}

// ---------------- final masked writeback + re-zero scratch for next call ----------------
__global__ void k_final(const float* __restrict__ linb,
                        const float* __restrict__ x,
                        const int* __restrict__ nmask,
                        const int* __restrict__ emask,
                        const int* __restrict__ ondp, const int* __restrict__ oedp,
                        float* __restrict__ out) {
    int i = blockIdx.x * blockDim.x + threadIdx.x;
    if (i < NN * 8) {
        int node = i >> 3;
        int c    = i & 7;
        float nv = g_out8[i] + linb[c];
        int ond = ondp[0];
        int oed = oedp[0];
        bool nm = nmask[node] != 0;
        bool em = emask[node] != 0;
        bool take = (nm && c >= 1 && c < ond + 1) || (em && c >= 1 && c < oed + 1);
        out[i] = take ? nv : x[i];
    }
    if (i < NN) g_cnt[i] = 0;
    if (i < LL * 64) g_stats[i] = 0.0f;
}

// ---------------- launch ----------------
extern "C" void kernel_launch(void* const* d_in, const int* in_sizes, int n_in,
                              void* d_out, int out_size) {
    const float* x     = (const float*)d_in[0];
    const float* t     = (const float*)d_in[1];
    const int*   ei    = (const int*)d_in[2];
    const int*   nmask = (const int*)d_in[3];
    const int*   emask = (const int*)d_in[4];
    const int*   ondp  = (const int*)d_in[5];
    const int*   oedp  = (const int*)d_in[6];
    const float* W1f   = (const float*)d_in[7];
    const float* b1f   = (const float*)d_in[8];
    const float* W2f   = (const float*)d_in[9];
    const float* b2f   = (const float*)d_in[10];
    const float* W1r   = (const float*)d_in[11];
    const float* b1r   = (const float*)d_in[12];
    const float* W2r   = (const float*)d_in[13];
    const float* b2r   = (const float*)d_in[14];
    const float* eps   = (const float*)d_in[15];
    const float* gamma = (const float*)d_in[16];
    const float* beta  = (const float*)d_in[17];
    const float* linW  = (const float*)d_in[18];
    const float* linb  = (const float*)d_in[19];
    float*       out   = (float*)d_out;

    const int* src = ei;
    const int* dst = ei + EE;
    const int TB = 256;

    k_init_hist<<<cdiv(EE, TB), TB>>>(x, t, dst);     // launch 0
    k_scan1<<<256, 1024>>>();                          // 1
    k_scan2<<<1, 256>>>();                             // 2
    k_scan3<<<cdiv(NN, TB), TB>>>();                   // 3
    k_fill<<<cdiv(EE, TB), TB>>>(src, dst);            // 4

    for (int l = 0; l < LL; l++) {
        if (l == 0) {
            k_agg_mlp9<<<AGG_BLOCKS, TB>>>(W1f, b1f, W2f, b2f, eps);   // 5 <- ncu target
        } else {
            k_agg_mlp32<<<AGG_BLOCKS, TB>>>(W1r + (l - 1) * 1024, b1r + (l - 1) * 32,
                                            W2r + (l - 1) * 1024, b2r + (l - 1) * 32,
                                            eps, l);
        }
        k_bn_proj<<<NN / 32, TB>>>(gamma + l * 32, beta + l * 32, linW, l);
    }

    k_final<<<cdiv(NN * 8, TB), TB>>>(linb, x, nmask, emask, ondp, oedp, out);
}

// round 10
// speedup vs baseline: 5.1100x; 1.1141x over previous
#include <cuda_runtime.h>
#include <cuda_bf16.h>

#define NN 262144
#define EE 4194304
#define LL 4
#define BN_EPS 1e-5f
#define AGG_BLOCKS 2048
#define AGG_PAIRS 8   // 8 iters * 2 nodes * 8 warps * 2048 blocks = NN

// ---------------- scratch (device globals; zero-initialized at module load,
// re-zeroed at tail of k_final each call so every invocation sees zeros) -----
__device__ float  g_h[NN * 32];     // layer input (stride 16 for layer 0, else 32)
__device__ float  g_z[NN * 32];     // pre-BN MLP output
__device__ float  g_out8[NN * 8];   // accumulated final projection
__device__ float  g_stats[LL * 64]; // per layer: [0:32) sum, [32:64) sumsq
__device__ int    g_cnt[NN];
__device__ int    g_row[NN + 1];
__device__ int    g_ofs[NN];
__device__ int    g_srcs[EE];
__device__ int    g_bsum[256];      // scan block totals (+1 ready encoding)

static inline int cdiv(int a, int b) { return (a + b - 1) / b; }

// ---------------- launch 0: init h0 (stride 16, zero-padded) + degree histogram ----
__global__ void k_init_hist(const float* __restrict__ x, const float* __restrict__ t,
                            const int* __restrict__ dst) {
    int i = blockIdx.x * blockDim.x + threadIdx.x;
    if (i < NN * 16) {
        int n = i >> 4;
        int c = i & 15;
        float v = 0.0f;
        if (c < 8)       v = x[n * 8 + c];
        else if (c == 8) v = t[0];
        g_h[i] = v;
    }
    if (i < EE) atomicAdd(&g_cnt[dst[i]], 1);
}

// ---------------- launch 1: fused exclusive scan (256 blocks x 1024 threads) ------
// Block publishes (total+1) to g_bsum[b] (nonzero == ready); every block sums all
// predecessor totals by polling. All 256 blocks are co-resident (launch_bounds 1024,2
// -> 296 slots on 148 SMs), so polling cannot deadlock.
__global__ void __launch_bounds__(1024, 2) k_scan_fused() {
    __shared__ int s[1024];
    int tid = threadIdx.x, b = blockIdx.x;
    int i = b * 1024 + tid;
    int v = g_cnt[i];
    s[tid] = v;
    __syncthreads();
    for (int off = 1; off < 1024; off <<= 1) {
        int tv = (tid >= off) ? s[tid - off] : 0;
        __syncthreads();
        s[tid] += tv;
        __syncthreads();
    }
    int incl = s[tid];                 // inclusive within block
    int excl_local = incl - v;         // exclusive within block
    if (tid == 1023) {
        // publish block total (+1 so 0 == not ready); word store is atomic
        atomicExch(&g_bsum[b], incl + 1);
    }
    // lookback: thread tid polls predecessor tid (tid < b)
    int pre = 0;
    if (tid < b) {
        volatile int* p = (volatile int*)&g_bsum[tid];
        int xv;
        while ((xv = *p) == 0) { }
        pre = xv - 1;
    }
    __syncthreads();                   // s[] reuse
    s[tid] = pre;
    __syncthreads();
    for (int off = 512; off >= 1; off >>= 1) {
        if (tid < off) s[tid] += s[tid + off];
        __syncthreads();
    }
    int base = s[0];
    int val = base + excl_local;
    g_row[i] = val;
    g_ofs[i] = val;
    if (i == 0) g_row[NN] = EE;
}

// ---------------- launch 2: CSR fill ----------------
__global__ void k_fill(const int* __restrict__ src, const int* __restrict__ dst) {
    int i = blockIdx.x * blockDim.x + threadIdx.x;
    if (i >= EE) return;
    int pos = atomicAdd(&g_ofs[dst[i]], 1);
    g_srcs[pos] = src[i];
}

// ---------------- launch 3 (ncu target): fused agg + MLP + BN-stats, layer 0 ------
__global__ void k_agg_mlp9(const float* __restrict__ W1, const float* __restrict__ b1,
                           const float* __restrict__ W2, const float* __restrict__ b2,
                           const float* __restrict__ epsp) {
    __shared__ __align__(16) float sW1T[32 * 36];
    __shared__ __align__(16) float sW2T[32 * 36];
    __shared__ __align__(16) float sZ[16 * 36];
    __shared__ float sb1[32], sb2[32];

    int tid = threadIdx.x;
    for (int i = tid; i < 32 * 16; i += blockDim.x) {
        int j = i >> 4, k = i & 15;
        sW1T[j * 36 + k] = (k < 9) ? W1[k * 32 + j] : 0.0f;
    }
    for (int i = tid; i < 32 * 32; i += blockDim.x) {
        int j = i >> 5, k = i & 31;
        sW2T[j * 36 + k] = W2[k * 32 + j];
    }
    if (tid < 32) { sb1[tid] = b1[tid]; sb2[tid] = b2[tid]; }
    __syncthreads();

    int w = tid >> 5, lane = tid & 31;
    int q = lane & 3;       // channel group (4 ch)
    int esub = lane >> 2;   // edge sub-slot 0..7
    float eps1 = 1.0f + epsp[0];

    float st_sum = 0.0f, st_sq = 0.0f;

    for (int it = 0; it < AGG_PAIRS; it++) {
        int nodeA = (blockIdx.x + it * AGG_BLOCKS) * 8 + w;
        int nodeB = nodeA + NN / 2;

        int sA = g_row[nodeA], eA = g_row[nodeA + 1];
        int sB = g_row[nodeB], eB = g_row[nodeB + 1];

        float4 accA = make_float4(0.f, 0.f, 0.f, 0.f);
        float4 accB = make_float4(0.f, 0.f, 0.f, 0.f);

        for (int base = sA; base < eA; base += 32) {
            int rem = eA - base;
#pragma unroll
            for (int jt = 0; jt < 4; jt++) {
                int e = jt * 8 + esub;
                if (e < rem) {
                    int s = g_srcs[base + e];
                    float4 v = *(const float4*)&g_h[s * 16 + q * 4];
                    accA.x += v.x; accA.y += v.y; accA.z += v.z; accA.w += v.w;
                }
            }
        }
        for (int base = sB; base < eB; base += 32) {
            int rem = eB - base;
#pragma unroll
            for (int jt = 0; jt < 4; jt++) {
                int e = jt * 8 + esub;
                if (e < rem) {
                    int s = g_srcs[base + e];
                    float4 v = *(const float4*)&g_h[s * 16 + q * 4];
                    accB.x += v.x; accB.y += v.y; accB.z += v.z; accB.w += v.w;
                }
            }
        }

        // reduce 8 edge sub-slots (partners differ in lane bits 2..4)
#pragma unroll
        for (int off = 4; off <= 16; off <<= 1) {
            accA.x += __shfl_xor_sync(0xffffffffu, accA.x, off);
            accA.y += __shfl_xor_sync(0xffffffffu, accA.y, off);
            accA.z += __shfl_xor_sync(0xffffffffu, accA.z, off);
            accA.w += __shfl_xor_sync(0xffffffffu, accA.w, off);
            accB.x += __shfl_xor_sync(0xffffffffu, accB.x, off);
            accB.y += __shfl_xor_sync(0xffffffffu, accB.y, off);
            accB.z += __shfl_xor_sync(0xffffffffu, accB.z, off);
            accB.w += __shfl_xor_sync(0xffffffffu, accB.w, off);
        }
        if (lane < 4) {
            float4 selfA = *(const float4*)&g_h[nodeA * 16 + lane * 4];
            float4 zA;
            zA.x = fmaf(eps1, selfA.x, accA.x);
            zA.y = fmaf(eps1, selfA.y, accA.y);
            zA.z = fmaf(eps1, selfA.z, accA.z);
            zA.w = fmaf(eps1, selfA.w, accA.w);
            *(float4*)&sZ[w * 36 + lane * 4] = zA;
            float4 selfB = *(const float4*)&g_h[nodeB * 16 + lane * 4];
            float4 zB;
            zB.x = fmaf(eps1, selfB.x, accB.x);
            zB.y = fmaf(eps1, selfB.y, accB.y);
            zB.z = fmaf(eps1, selfB.z, accB.z);
            zB.w = fmaf(eps1, selfB.w, accB.w);
            *(float4*)&sZ[(w + 8) * 36 + lane * 4] = zB;
        }
        __syncwarp();

        float a1 = sb1[lane];
        float b1v = sb1[lane];
#pragma unroll
        for (int k4 = 0; k4 < 16; k4 += 4) {
            float4 zvA = *(const float4*)&sZ[w * 36 + k4];
            float4 zvB = *(const float4*)&sZ[(w + 8) * 36 + k4];
            float4 wv  = *(const float4*)&sW1T[lane * 36 + k4];
            a1  = fmaf(zvA.x, wv.x, a1);  a1  = fmaf(zvA.y, wv.y, a1);
            a1  = fmaf(zvA.z, wv.z, a1);  a1  = fmaf(zvA.w, wv.w, a1);
            b1v = fmaf(zvB.x, wv.x, b1v); b1v = fmaf(zvB.y, wv.y, b1v);
            b1v = fmaf(zvB.z, wv.z, b1v); b1v = fmaf(zvB.w, wv.w, b1v);
        }
        a1  = fmaxf(a1, 0.0f);
        b1v = fmaxf(b1v, 0.0f);
        __syncwarp();
        sZ[w * 36 + lane] = a1;
        sZ[(w + 8) * 36 + lane] = b1v;
        __syncwarp();

        float a2 = sb2[lane];
        float b2v = sb2[lane];
#pragma unroll
        for (int k4 = 0; k4 < 32; k4 += 4) {
            float4 zvA = *(const float4*)&sZ[w * 36 + k4];
            float4 zvB = *(const float4*)&sZ[(w + 8) * 36 + k4];
            float4 wv  = *(const float4*)&sW2T[lane * 36 + k4];
            a2  = fmaf(zvA.x, wv.x, a2);  a2  = fmaf(zvA.y, wv.y, a2);
            a2  = fmaf(zvA.z, wv.z, a2);  a2  = fmaf(zvA.w, wv.w, a2);
            b2v = fmaf(zvB.x, wv.x, b2v); b2v = fmaf(zvB.y, wv.y, b2v);
            b2v = fmaf(zvB.z, wv.z, b2v); b2v = fmaf(zvB.w, wv.w, b2v);
        }
        g_z[nodeA * 32 + lane] = a2;
        g_z[nodeB * 32 + lane] = b2v;
        st_sum += a2 + b2v;
        st_sq  = fmaf(a2, a2, st_sq);
        st_sq  = fmaf(b2v, b2v, st_sq);
        __syncwarp();
    }

    __syncthreads();
    sW1T[w * 36 + lane] = st_sum;
    sW2T[w * 36 + lane] = st_sq;
    __syncthreads();
    if (tid < 32) {
        float s = 0.0f, qq = 0.0f;
#pragma unroll
        for (int ww = 0; ww < 8; ww++) {
            s  += sW1T[ww * 36 + tid];
            qq += sW2T[ww * 36 + tid];
        }
        atomicAdd(&g_stats[tid], s);
        atomicAdd(&g_stats[32 + tid], qq);
    }
}

// ---------------- fused agg + MLP + BN-stats, layers 1..3 (KIN=32) ----------------
__global__ void k_agg_mlp32(const float* __restrict__ W1, const float* __restrict__ b1,
                            const float* __restrict__ W2, const float* __restrict__ b2,
                            const float* __restrict__ epsp, int layer) {
    __shared__ __align__(16) float sW1T[32 * 36];
    __shared__ __align__(16) float sW2T[32 * 36];
    __shared__ __align__(16) float sZ[16 * 36];
    __shared__ float sb1[32], sb2[32];

    int tid = threadIdx.x;
    for (int i = tid; i < 32 * 32; i += blockDim.x) {
        int j = i >> 5, k = i & 31;
        sW1T[j * 36 + k] = W1[k * 32 + j];
        sW2T[j * 36 + k] = W2[k * 32 + j];
    }
    if (tid < 32) { sb1[tid] = b1[tid]; sb2[tid] = b2[tid]; }
    __syncthreads();

    int w = tid >> 5, lane = tid & 31;
    int q = lane & 7;        // channel group (4 ch)
    int esub = lane >> 3;    // edge sub-slot 0..3
    float eps1 = 1.0f + epsp[layer];

    float st_sum = 0.0f, st_sq = 0.0f;

    for (int it = 0; it < AGG_PAIRS; it++) {
        int nodeA = (blockIdx.x + it * AGG_BLOCKS) * 8 + w;
        int nodeB = nodeA + NN / 2;

        int sA = g_row[nodeA], eA = g_row[nodeA + 1];
        int sB = g_row[nodeB], eB = g_row[nodeB + 1];

        float4 accA = make_float4(0.f, 0.f, 0.f, 0.f);
        float4 accB = make_float4(0.f, 0.f, 0.f, 0.f);

        for (int base = sA; base < eA; base += 32) {
            int rem = eA - base;
#pragma unroll
            for (int jt = 0; jt < 8; jt++) {
                int e = jt * 4 + esub;
                if (e < rem) {
                    int s = g_srcs[base + e];
                    float4 v = *(const float4*)&g_h[s * 32 + q * 4];
                    accA.x += v.x; accA.y += v.y; accA.z += v.z; accA.w += v.w;
                }
            }
        }
        for (int base = sB; base < eB; base += 32) {
            int rem = eB - base;
#pragma unroll
            for (int jt = 0; jt < 8; jt++) {
                int e = jt * 4 + esub;
                if (e < rem) {
                    int s = g_srcs[base + e];
                    float4 v = *(const float4*)&g_h[s * 32 + q * 4];
                    accB.x += v.x; accB.y += v.y; accB.z += v.z; accB.w += v.w;
                }
            }
        }

#pragma unroll
        for (int off = 8; off <= 16; off <<= 1) {
            accA.x += __shfl_xor_sync(0xffffffffu, accA.x, off);
            accA.y += __shfl_xor_sync(0xffffffffu, accA.y, off);
            accA.z += __shfl_xor_sync(0xffffffffu, accA.z, off);
            accA.w += __shfl_xor_sync(0xffffffffu, accA.w, off);
            accB.x += __shfl_xor_sync(0xffffffffu, accB.x, off);
            accB.y += __shfl_xor_sync(0xffffffffu, accB.y, off);
            accB.z += __shfl_xor_sync(0xffffffffu, accB.z, off);
            accB.w += __shfl_xor_sync(0xffffffffu, accB.w, off);
        }
        if (lane < 8) {
            float4 selfA = *(const float4*)&g_h[nodeA * 32 + lane * 4];
            float4 zA;
            zA.x = fmaf(eps1, selfA.x, accA.x);
            zA.y = fmaf(eps1, selfA.y, accA.y);
            zA.z = fmaf(eps1, selfA.z, accA.z);
            zA.w = fmaf(eps1, selfA.w, accA.w);
            *(float4*)&sZ[w * 36 + lane * 4] = zA;
            float4 selfB = *(const float4*)&g_h[nodeB * 32 + lane * 4];
            float4 zB;
            zB.x = fmaf(eps1, selfB.x, accB.x);
            zB.y = fmaf(eps1, selfB.y, accB.y);
            zB.z = fmaf(eps1, selfB.z, accB.z);
            zB.w = fmaf(eps1, selfB.w, accB.w);
            *(float4*)&sZ[(w + 8) * 36 + lane * 4] = zB;
        }
        __syncwarp();

        float a1 = sb1[lane];
        float b1v = sb1[lane];
#pragma unroll
        for (int k4 = 0; k4 < 32; k4 += 4) {
            float4 zvA = *(const float4*)&sZ[w * 36 + k4];
            float4 zvB = *(const float4*)&sZ[(w + 8) * 36 + k4];
            float4 wv  = *(const float4*)&sW1T[lane * 36 + k4];
            a1  = fmaf(zvA.x, wv.x, a1);  a1  = fmaf(zvA.y, wv.y, a1);
            a1  = fmaf(zvA.z, wv.z, a1);  a1  = fmaf(zvA.w, wv.w, a1);
            b1v = fmaf(zvB.x, wv.x, b1v); b1v = fmaf(zvB.y, wv.y, b1v);
            b1v = fmaf(zvB.z, wv.z, b1v); b1v = fmaf(zvB.w, wv.w, b1v);
        }
        a1  = fmaxf(a1, 0.0f);
        b1v = fmaxf(b1v, 0.0f);
        __syncwarp();
        sZ[w * 36 + lane] = a1;
        sZ[(w + 8) * 36 + lane] = b1v;
        __syncwarp();

        float a2 = sb2[lane];
        float b2v = sb2[lane];
#pragma unroll
        for (int k4 = 0; k4 < 32; k4 += 4) {
            float4 zvA = *(const float4*)&sZ[w * 36 + k4];
            float4 zvB = *(const float4*)&sZ[(w + 8) * 36 + k4];
            float4 wv  = *(const float4*)&sW2T[lane * 36 + k4];
            a2  = fmaf(zvA.x, wv.x, a2);  a2  = fmaf(zvA.y, wv.y, a2);
            a2  = fmaf(zvA.z, wv.z, a2);  a2  = fmaf(zvA.w, wv.w, a2);
            b2v = fmaf(zvB.x, wv.x, b2v); b2v = fmaf(zvB.y, wv.y, b2v);
            b2v = fmaf(zvB.z, wv.z, b2v); b2v = fmaf(zvB.w, wv.w, b2v);
        }
        g_z[nodeA * 32 + lane] = a2;
        g_z[nodeB * 32 + lane] = b2v;
        st_sum += a2 + b2v;
        st_sq  = fmaf(a2, a2, st_sq);
        st_sq  = fmaf(b2v, b2v, st_sq);
        __syncwarp();
    }

    __syncthreads();
    sW1T[w * 36 + lane] = st_sum;
    sW2T[w * 36 + lane] = st_sq;
    __syncthreads();
    if (tid < 32) {
        float s = 0.0f, qq = 0.0f;
#pragma unroll
        for (int ww = 0; ww < 8; ww++) {
            s  += sW1T[ww * 36 + tid];
            qq += sW2T[ww * 36 + tid];
        }
        atomicAdd(&g_stats[layer * 64 + tid], s);
        atomicAdd(&g_stats[layer * 64 + 32 + tid], qq);
    }
}

// ---------------- BN apply (+ReLU) + per-layer projection into g_out8 ----------------
// 256 threads, 32 nodes/block; float4 streaming, smem stride 40 (16B-aligned rows).
__global__ void k_bn_proj(const float* __restrict__ gamma, const float* __restrict__ beta,
                          const float* __restrict__ linW, int layer) {
    __shared__ __align__(16) float sV[32 * 40];
    __shared__ float sW[32 * 8];
    __shared__ float sScale[32], sShift[32];

    int tid = threadIdx.x;
    int node0 = blockIdx.x * 32;

    sW[tid] = linW[layer * 32 * 8 + tid];
    if (tid < 32) {
        float inv_n = 1.0f / (float)NN;
        float mu  = g_stats[layer * 64 + tid] * inv_n;
        float var = g_stats[layer * 64 + 32 + tid] * inv_n - mu * mu;
        float scale = gamma[tid] * rsqrtf(var + BN_EPS);
        sScale[tid] = scale;
        sShift[tid] = beta[tid] - mu * scale;
    }
    __syncthreads();

    {
        int node = tid >> 3;       // 0..31
        int grp  = tid & 7;        // float4 group
        float4 z = *(const float4*)&g_z[(node0 + node) * 32 + grp * 4];
        float4 o;
#pragma unroll
        for (int j = 0; j < 4; j++) {
            int ch = grp * 4 + j;
            (&o.x)[j] = fmaxf(fmaf((&z.x)[j], sScale[ch], sShift[ch]), 0.0f);
        }
        *(float4*)&g_h[(node0 + node) * 32 + grp * 4] = o;
        *(float4*)&sV[node * 40 + grp * 4] = o;
    }
    __syncthreads();

    int node = tid >> 3;
    int o    = tid & 7;
    float acc = 0.0f;
#pragma unroll
    for (int k = 0; k < 32; k++)
        acc = fmaf(sV[node * 40 + k], sW[k * 8 + o], acc);

    int gi = node0 * 8 + tid;
    if (layer == 0) g_out8[gi] = acc;
    else            g_out8[gi] += acc;
}

// ---------------- final masked writeback + re-zero scratch for next call ----------------
__global__ void k_final(const float* __restrict__ linb,
                        const float* __restrict__ x,
                        const int* __restrict__ nmask,
                        const int* __restrict__ emask,
                        const int* __restrict__ ondp, const int* __restrict__ oedp,
                        float* __restrict__ out) {
    int i = blockIdx.x * blockDim.x + threadIdx.x;
    if (i < NN * 8) {
        int node = i >> 3;
        int c    = i & 7;
        float nv = g_out8[i] + linb[c];
        int ond = ondp[0];
        int oed = oedp[0];
        bool nm = nmask[node] != 0;
        bool em = emask[node] != 0;
        bool take = (nm && c >= 1 && c < ond + 1) || (em && c >= 1 && c < oed + 1);
        out[i] = take ? nv : x[i];
    }
    if (i < NN) g_cnt[i] = 0;
    if (i < LL * 64) g_stats[i] = 0.0f;
    if (i < 256) g_bsum[i] = 0;
}

// ---------------- launch ----------------
extern "C" void kernel_launch(void* const* d_in, const int* in_sizes, int n_in,
                              void* d_out, int out_size) {
    const float* x     = (const float*)d_in[0];
    const float* t     = (const float*)d_in[1];
    const int*   ei    = (const int*)d_in[2];
    const int*   nmask = (const int*)d_in[3];
    const int*   emask = (const int*)d_in[4];
    const int*   ondp  = (const int*)d_in[5];
    const int*   oedp  = (const int*)d_in[6];
    const float* W1f   = (const float*)d_in[7];
    const float* b1f   = (const float*)d_in[8];
    const float* W2f   = (const float*)d_in[9];
    const float* b2f   = (const float*)d_in[10];
    const float* W1r   = (const float*)d_in[11];
    const float* b1r   = (const float*)d_in[12];
    const float* W2r   = (const float*)d_in[13];
    const float* b2r   = (const float*)d_in[14];
    const float* eps   = (const float*)d_in[15];
    const float* gamma = (const float*)d_in[16];
    const float* beta  = (const float*)d_in[17];
    const float* linW  = (const float*)d_in[18];
    const float* linb  = (const float*)d_in[19];
    float*       out   = (float*)d_out;

    const int* src = ei;
    const int* dst = ei + EE;
    const int TB = 256;

    k_init_hist<<<cdiv(EE, TB), TB>>>(x, t, dst);      // launch 0
    k_scan_fused<<<256, 1024>>>();                     // launch 1
    k_fill<<<cdiv(EE, TB), TB>>>(src, dst);            // launch 2

    for (int l = 0; l < LL; l++) {
        if (l == 0) {
            k_agg_mlp9<<<AGG_BLOCKS, TB>>>(W1f, b1f, W2f, b2f, eps);   // launch 3 <- ncu
        } else {
            k_agg_mlp32<<<AGG_BLOCKS, TB>>>(W1r + (l - 1) * 1024, b1r + (l - 1) * 32,
                                            W2r + (l - 1) * 1024, b2r + (l - 1) * 32,
                                            eps, l);
        }
        k_bn_proj<<<NN / 32, TB>>>(gamma + l * 32, beta + l * 32, linW, l);
    }

    k_final<<<cdiv(NN * 8, TB), TB>>>(linb, x, nmask, emask, ondp, oedp, out);
}